// round 4
// baseline (speedup 1.0000x reference)
#include <cuda_runtime.h>
#include <math.h>

#define Vv 18000
#define Hh 400
#define Bb 16
#define TENC 256
#define Ss 30
#define TDEC 8
#define Gg 3
#define SB 480
#define H3 1200
#define PTR_OUT 69120000L

// ---------------- scratch: one big __device__ array + offsets ----------------
#define OX    0L
#define OGI0  1638400L
#define OGI1  6553600L
#define OHF   11468800L
#define OHB   13107200L
#define OEO   14745600L
#define OEOT  16384000L
#define OH    18022400L
#define ODIN  18214400L
#define OGI   18406400L
#define OGH   18982400L
#define OPROB 19558400L
#define OCTX  19681280L
#define OSW   19873280L
#define ORMX  19873760L
#define ORSC  19874240L
#define OLOG  19874720L
#define STOT  28514720L

__device__ float d_S[STOT];
__device__ float d_Hbuf[2][2][Bb * Hh];   // [dir][parity][16*400]
__device__ unsigned g_barcnt, g_bargen;

// ---------------- fast exp (FMA-only, rel err ~1e-7) ----------------
__device__ __forceinline__ float fexp(float x) {
    x = fminf(fmaxf(x, -80.0f), 80.0f);
    float y = x * 1.4426950408889634f;
    int   i = __float2int_rn(y);
    float f = y - (float)i;
    float u = f * 0.6931471805599453f;
    float p = 1.0f + u * (1.0f + u * (0.5f + u * (0.16666667f +
              u * (0.041666668f + u * (0.008333334f + u * 0.0013888889f)))));
    return __int_as_float(__float_as_int(p) + (i << 23));
}
__device__ __forceinline__ float fsig(float x) { return 1.0f / (1.0f + fexp(-x)); }

// ---------------- init ----------------
__global__ void k_init() {
    int tid = blockIdx.x * blockDim.x + threadIdx.x;
    if (tid == 0) { g_barcnt = 0u; g_bargen = 0u; }
    for (int i = tid; i < 2 * 2 * Bb * Hh; i += gridDim.x * blockDim.x)
        ((float*)d_Hbuf)[i] = 0.0f;
}

// ---------------- embed story: d_X[t][b][h] ----------------
__global__ void k_embed(const int* __restrict__ story, const float* __restrict__ emb) {
    long idx = (long)blockIdx.x * blockDim.x + threadIdx.x;
    if (idx >= (long)TENC * Bb * Hh) return;
    int h = (int)(idx % Hh);
    int tb = (int)(idx / Hh);
    int b = tb & 15, t = tb >> 4;
    d_S[OX + idx] = emb[(long)story[b * TENC + t] * Hh + h];
}

// ---------------- generic batched TN SGEMM: C = A @ Bw^T (+bias) ----------------
// 64x64x16 tile, 256 threads, 4x4 per thread. K % 16 == 0, all k-strides % 4 == 0.
__global__ void __launch_bounds__(256) k_sgemm(
    const float* __restrict__ A, int lda, long sA,
    const float* __restrict__ Bw, int ldb, long sB,
    const float* __restrict__ bias,
    float* __restrict__ C, int ldc, long sC,
    int M, int N, int K)
{
    A  += (long)blockIdx.z * sA;
    Bw += (long)blockIdx.z * sB;
    C  += (long)blockIdx.z * sC;
    __shared__ float As[16][68];
    __shared__ float Bs[16][68];
    int tid = threadIdx.x;
    int tx = tid & 15, ty = tid >> 4;
    int row0 = blockIdx.y * 64, col0 = blockIdx.x * 64;
    int lm = tid >> 2, lk = (tid & 3) << 2;
    float acc[4][4] = {{0.f}};

    for (int k0 = 0; k0 < K; k0 += 16) {
        float4 va = make_float4(0.f, 0.f, 0.f, 0.f);
        float4 vb = make_float4(0.f, 0.f, 0.f, 0.f);
        if (row0 + lm < M) va = *(const float4*)(A + (long)(row0 + lm) * lda + k0 + lk);
        if (col0 + lm < N) vb = *(const float4*)(Bw + (long)(col0 + lm) * ldb + k0 + lk);
        __syncthreads();
        As[lk][lm] = va.x; As[lk+1][lm] = va.y; As[lk+2][lm] = va.z; As[lk+3][lm] = va.w;
        Bs[lk][lm] = vb.x; Bs[lk+1][lm] = vb.y; Bs[lk+2][lm] = vb.z; Bs[lk+3][lm] = vb.w;
        __syncthreads();
#pragma unroll
        for (int kk = 0; kk < 16; kk++) {
            float4 a = *(const float4*)&As[kk][ty << 2];
            float4 b = *(const float4*)&Bs[kk][tx << 2];
            acc[0][0] += a.x*b.x; acc[0][1] += a.x*b.y; acc[0][2] += a.x*b.z; acc[0][3] += a.x*b.w;
            acc[1][0] += a.y*b.x; acc[1][1] += a.y*b.y; acc[1][2] += a.y*b.z; acc[1][3] += a.y*b.w;
            acc[2][0] += a.z*b.x; acc[2][1] += a.z*b.y; acc[2][2] += a.z*b.z; acc[2][3] += a.z*b.w;
            acc[3][0] += a.w*b.x; acc[3][1] += a.w*b.y; acc[3][2] += a.w*b.z; acc[3][3] += a.w*b.w;
        }
    }
#pragma unroll
    for (int i = 0; i < 4; i++) {
        int gm = row0 + (ty << 2) + i;
        if (gm >= M) continue;
#pragma unroll
        for (int j = 0; j < 4; j++) {
            int gn = col0 + (tx << 2) + j;
            if (gn >= N) continue;
            float v = acc[i][j];
            if (bias) v += __ldg(&bias[gn]);
            C[(long)gm * ldc + gn] = v;
        }
    }
}

// ---------------- persistent bi-GRU encoder ----------------
// 100 blocks (<=148 SMs, single wave, spin grid barrier), 384 threads.
// block: dir = bid/50, 8 j-columns. Whh tile (24 rows x 400) cached in SMEM once.
__global__ void __launch_bounds__(384, 1) k_enc(
    const float* __restrict__ Whh_f, const float* __restrict__ Whh_b,
    const float* __restrict__ bhh_f, const float* __restrict__ bhh_b)
{
    extern __shared__ float sm[];
    float* Wt  = sm;                   // 24*400 = 9600
    float* hs  = sm + 9600;            // 16*404 = 6464
    float* ghs = sm + 9600 + 6464;     // 24*16  = 384
    float* bsh = ghs + 384;            // 24

    unsigned nblk = gridDim.x;
    int dir = (int)(blockIdx.x / (nblk / 2));
    int jb  = (int)(blockIdx.x % (nblk / 2));
    int j0  = jb * 8;
    const float* Whh = dir ? Whh_b : Whh_f;
    const float* bhh = dir ? bhh_b : bhh_f;
    const float* GI  = d_S + (dir ? OGI1 : OGI0);
    float* OUT = d_S + (dir ? OHB : OHF);
    int tid = threadIdx.x;

    for (int i = tid; i < 24 * 400; i += 384) {
        int q = i / 400, k = i % 400;
        int gate = q >> 3, jl = q & 7;
        Wt[i] = Whh[(long)(gate * 400 + j0 + jl) * 400 + k];
    }
    if (tid < 24) { int gate = tid >> 3, jl = tid & 7; bsh[tid] = bhh[gate * 400 + j0 + jl]; }
    __syncthreads();

    int q = tid >> 4, r = tid & 15;
    const float* Wrow = Wt + q * 400;

    for (int t = 0; t < TENC; ++t) {
        int p = t & 1;
        const float* Hin = d_Hbuf[dir][p];
        float* Hout = d_Hbuf[dir][p ^ 1];

        for (int i = tid; i < 6400; i += 384) hs[(i / 400) * 404 + (i % 400)] = Hin[i];
        __syncthreads();

        float a0 = 0.f, a1 = 0.f, a2 = 0.f, a3 = 0.f;
        const float* hrow = hs + r * 404;
#pragma unroll 4
        for (int k = 0; k < 400; k += 4) {
            float4 hv = *(const float4*)(hrow + k);
            float4 wv = *(const float4*)(Wrow + k);
            a0 += hv.x * wv.x; a1 += hv.y * wv.y; a2 += hv.z * wv.z; a3 += hv.w * wv.w;
        }
        ghs[q * 16 + r] = (a0 + a1) + (a2 + a3) + bsh[q];
        __syncthreads();

        if (tid < 128) {
            int rr = tid & 15, jj = tid >> 4;   // jj 0..7
            int time = dir ? (TENC - 1 - t) : t;
            long gib = ((long)time * Bb + rr) * H3 + j0 + jj;
            float ir = GI[gib], iz = GI[gib + 400], ig = GI[gib + 800];
            float hr_ = ghs[jj * 16 + rr];
            float hz_ = ghs[(8 + jj) * 16 + rr];
            float hg_ = ghs[(16 + jj) * 16 + rr];
            float hp  = hs[rr * 404 + j0 + jj];
            float rg = fsig(ir + hr_);
            float zg = fsig(iz + hz_);
            float gg = tanhf(ig + rg * hg_);
            float hn = (1.f - zg) * gg + zg * hp;
            Hout[rr * 400 + j0 + jj] = hn;
            OUT[((long)time * Bb + rr) * Hh + j0 + jj] = hn;
        }
        __threadfence();
        __syncthreads();
        if (tid == 0) {
            unsigned a = atomicAdd(&g_barcnt, 1u);
            if (a == nblk * (unsigned)(t + 1) - 1u) {
                __threadfence();
                atomicAdd(&g_bargen, 1u);
            } else {
                while (*(volatile unsigned*)&g_bargen < (unsigned)(t + 1)) { __nanosleep(64); }
            }
            __threadfence();
        }
        __syncthreads();
    }
}

// ---------------- enc_out (B,T,H) and its transpose (B,H,T) ----------------
__global__ void k_encout() {
    long idx = (long)blockIdx.x * blockDim.x + threadIdx.x;
    if (idx >= (long)Bb * TENC * Hh) return;
    int b = (int)(idx / (TENC * Hh));
    int rem = (int)(idx % (TENC * Hh));
    int t = rem / Hh, h = rem % Hh;
    long src = ((long)t * Bb + b) * Hh + h;
    float v = d_S[OHF + src] + d_S[OHB + src];
    d_S[OEO + idx] = v;
    d_S[OEOT + (long)b * (Hh * TENC) + (long)h * TENC + t] = v;
}

// ---------------- decoder init: h = enc_hidden[b], din = slot_emb[s] ----------------
__global__ void k_dec_init(const float* __restrict__ slot) {
    int idx = blockIdx.x * blockDim.x + threadIdx.x;
    if (idx >= SB * Hh) return;
    int n = idx / Hh, h = idx % Hh;
    int s = n >> 4, b = n & 15;
    d_S[OH + idx]   = d_S[OHF + ((long)(TENC - 1) * Bb + b) * Hh + h]
                    + d_S[OHB + ((long)b) * Hh + h];
    d_S[ODIN + idx] = slot[s * Hh + h];
}

// ---------------- decoder GRU gates (in-place update of h) ----------------
__global__ void k_dec_gates() {
    int idx = blockIdx.x * blockDim.x + threadIdx.x;
    if (idx >= SB * Hh) return;
    int n = idx / Hh, j = idx % Hh;
    long gb = (long)n * H3 + j;
    float ir = d_S[OGI + gb], iz = d_S[OGI + gb + 400], ig = d_S[OGI + gb + 800];
    float hr = d_S[OGH + gb], hz = d_S[OGH + gb + 400], hg = d_S[OGH + gb + 800];
    float hp = d_S[OH + idx];
    float r = fsig(ir + hr);
    float z = fsig(iz + hz);
    float g = tanhf(ig + r * hg);
    d_S[OH + idx] = (1.f - z) * g + z * hp;
}

// ---------------- attention softmax over T=256 ----------------
__global__ void k_softmax_att() {
    int n = blockIdx.x, tid = threadIdx.x;
    __shared__ float red[256];
    float x = d_S[OPROB + (long)n * TENC + tid];
    red[tid] = x; __syncthreads();
    for (int o = 128; o; o >>= 1) { if (tid < o) red[tid] = fmaxf(red[tid], red[tid + o]); __syncthreads(); }
    float m = red[0]; __syncthreads();
    float e = fexp(x - m);
    red[tid] = e; __syncthreads();
    for (int o = 128; o; o >>= 1) { if (tid < o) red[tid] += red[tid + o]; __syncthreads(); }
    d_S[OPROB + (long)n * TENC + tid] = e / red[0];
}

// ---------------- sw (p_gen ratio) and (t==0) gate outputs ----------------
__global__ void k_sw_gate(const float* __restrict__ Wr, const float* __restrict__ br,
                          const float* __restrict__ Wg, const float* __restrict__ bg,
                          float* __restrict__ out, int t) {
    int warp = (blockIdx.x * blockDim.x + threadIdx.x) >> 5;
    int lane = threadIdx.x & 31;
    if (warp >= SB) return;
    int n = warp;
    float s = 0.f;
    for (int j = lane; j < H3; j += 32) {
        float v = (j < 400) ? d_S[OH + (long)n * Hh + j]
                : (j < 800) ? d_S[OCTX + (long)n * Hh + j - 400]
                            : d_S[ODIN + (long)n * Hh + j - 800];
        s += v * Wr[j];
    }
    for (int o = 16; o; o >>= 1) s += __shfl_xor_sync(0xffffffffu, s, o);
    if (lane == 0) d_S[OSW + n] = fsig(s + br[0]);
    if (t == 0) {
        for (int g = 0; g < Gg; g++) {
            float a = 0.f;
            for (int j = lane; j < Hh; j += 32) a += d_S[OCTX + (long)n * Hh + j] * Wg[g * Hh + j];
            for (int o = 16; o; o >>= 1) a += __shfl_xor_sync(0xffffffffu, a, o);
            if (lane == 0) out[PTR_OUT + (long)n * Gg + g] = a + bg[g];
        }
    }
}

// ---------------- per-row max & sum of exp over V logits ----------------
__global__ void k_rowstat() {
    int n = blockIdx.x, tid = threadIdx.x;
    const float* L = d_S + OLOG + (long)n * Vv;
    float m = -1e30f, s = 0.f;
    for (int v = tid; v < Vv; v += 256) {
        float x = L[v];
        if (x > m) { s = s * fexp(m - x) + 1.f; m = x; }
        else       { s += fexp(x - m); }
    }
    __shared__ float sm_[256], ss_[256];
    sm_[tid] = m; ss_[tid] = s; __syncthreads();
    for (int o = 128; o; o >>= 1) {
        if (tid < o) {
            float m2 = sm_[tid + o], s2 = ss_[tid + o];
            float mm = fmaxf(sm_[tid], m2);
            ss_[tid] = ss_[tid] * fexp(sm_[tid] - mm) + s2 * fexp(m2 - mm);
            sm_[tid] = mm;
        }
        __syncthreads();
    }
    if (tid == 0) { d_S[ORMX + n] = sm_[0]; d_S[ORSC + n] = d_S[OSW + n] / ss_[0]; }
}

// ---------------- write sw * p_vocab ----------------
__global__ void k_final(float* __restrict__ out, int t) {
    long idx = (long)blockIdx.x * blockDim.x + threadIdx.x;   // float4 index
    if (idx >= (long)SB * (Vv / 4)) return;
    int n = (int)(idx / (Vv / 4));
    int c = (int)(idx % (Vv / 4)) * 4;
    float4 l = *(const float4*)(d_S + OLOG + (long)n * Vv + c);
    float m = d_S[ORMX + n], sc = d_S[ORSC + n];
    float4 o;
    o.x = fexp(l.x - m) * sc;
    o.y = fexp(l.y - m) * sc;
    o.z = fexp(l.z - m) * sc;
    o.w = fexp(l.w - m) * sc;
    *(float4*)(out + ((long)n * TDEC + t) * Vv + c) = o;
}

// ---------------- scatter-add pointer distribution ----------------
__global__ void k_scatter(float* __restrict__ out, const int* __restrict__ story, int t) {
    int idx = blockIdx.x * blockDim.x + threadIdx.x;
    if (idx >= SB * TENC) return;
    int n = idx >> 8, tt = idx & 255;
    int b = n & 15;
    int tok = story[b * TENC + tt];
    float v = (1.f - d_S[OSW + n]) * d_S[OPROB + (long)n * TENC + tt];
    atomicAdd(out + ((long)n * TDEC + t) * Vv + tok, v);
}

// ---------------- next decoder input: emb[tf_tokens[t]] ----------------
__global__ void k_next_din(const int* __restrict__ tb, const float* __restrict__ emb, int t) {
    int idx = blockIdx.x * blockDim.x + threadIdx.x;
    if (idx >= SB * Hh) return;
    int n = idx / Hh, h = idx % Hh;
    int s = n >> 4, b = n & 15;
    int tok = tb[(b * Ss + s) * TDEC + t];
    d_S[ODIN + idx] = emb[(long)tok * Hh + h];
}

// ---------------- host ----------------
extern "C" void kernel_launch(void* const* d_in, const int* in_sizes, int n_in,
                              void* d_out, int out_size) {
    const int*   story = (const int*)d_in[0];
    const int*   tb    = (const int*)d_in[1];
    const float* emb   = (const float*)d_in[2];
    const float* eWif  = (const float*)d_in[3];
    const float* eWhf  = (const float*)d_in[4];
    const float* ebif  = (const float*)d_in[5];
    const float* ebhf  = (const float*)d_in[6];
    const float* eWib  = (const float*)d_in[7];
    const float* eWhb  = (const float*)d_in[8];
    const float* ebib  = (const float*)d_in[9];
    const float* ebhb  = (const float*)d_in[10];
    const float* dWi   = (const float*)d_in[11];
    const float* dWh   = (const float*)d_in[12];
    const float* dbi   = (const float*)d_in[13];
    const float* dbh   = (const float*)d_in[14];
    const float* Wr    = (const float*)d_in[15];
    const float* br    = (const float*)d_in[16];
    const float* Wg    = (const float*)d_in[17];
    const float* bg    = (const float*)d_in[18];
    const float* slot  = (const float*)d_in[19];
    float* out = (float*)d_out;

    static int smem_set = 0;
    if (!smem_set) {
        cudaFuncSetAttribute(k_enc, cudaFuncAttributeMaxDynamicSharedMemorySize, 66000);
        smem_set = 1;
    }

    float* S = nullptr;
    cudaGetSymbolAddress((void**)&S, d_S);
    float* pX    = S + OX;
    float* pGI0  = S + OGI0;
    float* pGI1  = S + OGI1;
    float* pEO   = S + OEO;
    float* pEOT  = S + OEOT;
    float* pH    = S + OH;
    float* pDIN  = S + ODIN;
    float* pGI   = S + OGI;
    float* pGH   = S + OGH;
    float* pPROB = S + OPROB;
    float* pCTX  = S + OCTX;
    float* pLOG  = S + OLOG;

    k_init<<<32, 256>>>();
    k_embed<<<(TENC * Bb * Hh + 255) / 256, 256>>>(story, emb);

    // GI (input gates) for both encoder directions: (4096 x 1200 x 400)
    k_sgemm<<<dim3(19, 64, 1), 256>>>(pX, Hh, 0, eWif, Hh, 0, ebif, pGI0, H3, 0, TENC * Bb, H3, Hh);
    k_sgemm<<<dim3(19, 64, 1), 256>>>(pX, Hh, 0, eWib, Hh, 0, ebib, pGI1, H3, 0, TENC * Bb, H3, Hh);

    // persistent bidirectional GRU
    k_enc<<<100, 384, 66000>>>(eWhf, eWhb, ebhf, ebhb);

    k_encout<<<(Bb * TENC * Hh + 255) / 256, 256>>>();
    k_dec_init<<<(SB * Hh + 255) / 256, 256>>>(slot);

    for (int t = 0; t < TDEC; t++) {
        // GRU: gi = din@Wih^T+bih ; gh = h@Whh^T+bhh ; gates
        k_sgemm<<<dim3(19, 8, 1), 256>>>(pDIN, Hh, 0, dWi, Hh, 0, dbi, pGI, H3, 0, SB, H3, Hh);
        k_sgemm<<<dim3(19, 8, 1), 256>>>(pH,   Hh, 0, dWh, Hh, 0, dbh, pGH, H3, 0, SB, H3, Hh);
        k_dec_gates<<<(SB * Hh + 255) / 256, 256>>>();

        // attention: scores (batched over b), softmax, context (batched over b)
        k_sgemm<<<dim3(4, 1, Bb), 256>>>(pH, Bb * Hh, Hh, pEO, Hh, (long)TENC * Hh,
                                         nullptr, pPROB, Bb * TENC, TENC, Ss, TENC, Hh);
        k_softmax_att<<<SB, 256>>>();
        k_sgemm<<<dim3(7, 1, Bb), 256>>>(pPROB, Bb * TENC, TENC, pEOT, TENC, (long)Hh * TENC,
                                         nullptr, pCTX, Bb * Hh, Hh, Ss, Hh, TENC);

        k_sw_gate<<<60, 256>>>(Wr, br, Wg, bg, out, t);

        // vocab logits + softmax + fused output write
        k_sgemm<<<dim3(282, 8, 1), 256>>>(pH, Hh, 0, emb, Hh, 0, nullptr, pLOG, Vv, 0, SB, Vv, Hh);
        k_rowstat<<<SB, 256>>>();
        k_final<<<(SB * (Vv / 4) + 255) / 256, 256>>>(out, t);
        k_scatter<<<SB, 256>>>(out, story, t);

        k_next_din<<<(SB * Hh + 255) / 256, 256>>>(tb, emb, t);
    }
}

// round 5
// speedup vs baseline: 1.1167x; 1.1167x over previous
#include <cuda_runtime.h>
#include <math.h>

#define Vv 18000
#define Hh 400
#define Bb 16
#define TENC 256
#define Ss 30
#define TDEC 8
#define Gg 3
#define SB 480
#define H3 1200
#define PTR_OUT 69120000L

// ---------------- scratch: one big __device__ array + offsets ----------------
#define OX    0L
#define OGI0  1638400L
#define OGI1  6553600L
#define OHF   11468800L
#define OHB   13107200L
#define OEO   14745600L
#define OEOT  16384000L
#define OH    18022400L
#define ODIN  18214400L
#define OGI   18406400L
#define OGH   18982400L
#define OPROB 19558400L
#define OCTX  19681280L
#define OSW   19873280L
#define ORSUM 19873760L
#define OLOG  19874720L
#define STOT  28514720L

__device__ float d_S[STOT];
__device__ float d_Hbuf[2][2][Bb * Hh];   // [dir][parity][16*400]
__device__ unsigned g_barcnt[2], g_bargen[2];

// ---------------- fast exp (FMA-only, rel err ~1e-7) ----------------
__device__ __forceinline__ float fexp(float x) {
    x = fminf(fmaxf(x, -80.0f), 80.0f);
    float y = x * 1.4426950408889634f;
    int   i = __float2int_rn(y);
    float f = y - (float)i;
    float u = f * 0.6931471805599453f;
    float p = 1.0f + u * (1.0f + u * (0.5f + u * (0.16666667f +
              u * (0.041666668f + u * (0.008333334f + u * 0.0013888889f)))));
    return __int_as_float(__float_as_int(p) + (i << 23));
}
__device__ __forceinline__ float fsig(float x) { return 1.0f / (1.0f + fexp(-x)); }

// ---------------- init ----------------
__global__ void k_init() {
    int tid = blockIdx.x * blockDim.x + threadIdx.x;
    if (tid == 0) {
        g_barcnt[0] = 0u; g_barcnt[1] = 0u;
        g_bargen[0] = 0u; g_bargen[1] = 0u;
    }
    for (int i = tid; i < 2 * 2 * Bb * Hh; i += gridDim.x * blockDim.x)
        ((float*)d_Hbuf)[i] = 0.0f;
}

// ---------------- embed story: d_X[t][b][h] ----------------
__global__ void k_embed(const int* __restrict__ story, const float* __restrict__ emb) {
    long idx = (long)blockIdx.x * blockDim.x + threadIdx.x;
    if (idx >= (long)TENC * Bb * Hh) return;
    int h = (int)(idx % Hh);
    int tb = (int)(idx / Hh);
    int b = tb & 15, t = tb >> 4;
    d_S[OX + idx] = emb[(long)story[b * TENC + t] * Hh + h];
}

// ---------------- 128x128x8 double-buffered TN SGEMM ----------------
// C = A[M,K] @ Bw[N,K]^T (+bias). Optional epilogue: rowsum[gm] += sum_j fexp(C[gm][j]).
// 256 threads, 8x8 per thread (split-tile frags), K % 8 == 0.
__global__ void __launch_bounds__(256) k_gemm128(
    const float* __restrict__ A, int lda,
    const float* __restrict__ Bw, int ldb,
    const float* __restrict__ bias,
    float* __restrict__ C, int ldc,
    float* __restrict__ rowsum,
    int M, int N, int K)
{
    __shared__ float As[2][8][132];
    __shared__ float Bs[2][8][132];
    int tid = threadIdx.x;
    int tx = tid & 15, ty = tid >> 4;
    int row0 = blockIdx.y * 128, col0 = blockIdx.x * 128;
    int lm = tid >> 1, lk = (tid & 1) << 2;

    bool av = (row0 + lm) < M;
    bool bv = (col0 + lm) < N;
    const float* Ap = A + (long)(row0 + lm) * lda + lk;
    const float* Bp = Bw + (long)(col0 + lm) * ldb + lk;
    const float4 z4 = make_float4(0.f, 0.f, 0.f, 0.f);

    float4 va = av ? *(const float4*)Ap : z4;
    float4 vb = bv ? *(const float4*)Bp : z4;
    As[0][lk + 0][lm] = va.x; As[0][lk + 1][lm] = va.y; As[0][lk + 2][lm] = va.z; As[0][lk + 3][lm] = va.w;
    Bs[0][lk + 0][lm] = vb.x; Bs[0][lk + 1][lm] = vb.y; Bs[0][lk + 2][lm] = vb.z; Bs[0][lk + 3][lm] = vb.w;
    __syncthreads();

    float acc[8][8];
#pragma unroll
    for (int i = 0; i < 8; i++)
#pragma unroll
        for (int j = 0; j < 8; j++) acc[i][j] = 0.f;

    int KT = K >> 3;
    for (int kt = 0; kt < KT; kt++) {
        int bf = kt & 1;
        float4 nva, nvb;
        if (kt + 1 < KT) {
            nva = av ? *(const float4*)(Ap + (kt + 1) * 8) : z4;
            nvb = bv ? *(const float4*)(Bp + (kt + 1) * 8) : z4;
        }
#pragma unroll
        for (int kk = 0; kk < 8; kk++) {
            float a[8], b[8];
            *(float4*)(a)     = *(const float4*)&As[bf][kk][ty << 2];
            *(float4*)(a + 4) = *(const float4*)&As[bf][kk][64 + (ty << 2)];
            *(float4*)(b)     = *(const float4*)&Bs[bf][kk][tx << 2];
            *(float4*)(b + 4) = *(const float4*)&Bs[bf][kk][64 + (tx << 2)];
#pragma unroll
            for (int i = 0; i < 8; i++)
#pragma unroll
                for (int j = 0; j < 8; j++) acc[i][j] += a[i] * b[j];
        }
        if (kt + 1 < KT) {
            int nb = bf ^ 1;
            As[nb][lk + 0][lm] = nva.x; As[nb][lk + 1][lm] = nva.y; As[nb][lk + 2][lm] = nva.z; As[nb][lk + 3][lm] = nva.w;
            Bs[nb][lk + 0][lm] = nvb.x; Bs[nb][lk + 1][lm] = nvb.y; Bs[nb][lk + 2][lm] = nvb.z; Bs[nb][lk + 3][lm] = nvb.w;
            __syncthreads();
        }
    }

#pragma unroll
    for (int i = 0; i < 8; i++) {
        int gm = row0 + ((i < 4) ? (ty << 2) + i : 64 + (ty << 2) + i - 4);
        bool rv = gm < M;
        float s = 0.f;
#pragma unroll
        for (int j = 0; j < 8; j++) {
            int gn = col0 + ((j < 4) ? (tx << 2) + j : 64 + (tx << 2) + j - 4);
            if (gn < N) {
                float v = acc[i][j];
                if (bias) v += __ldg(&bias[gn]);
                if (rv) C[(long)gm * ldc + gn] = v;
                if (rowsum) s += fexp(v);
            }
        }
        if (rowsum) {
#pragma unroll
            for (int o = 8; o; o >>= 1) s += __shfl_xor_sync(0xffffffffu, s, o);
            if (tx == 0 && rv) atomicAdd(rowsum + gm, s);
        }
    }
}

// ---------------- generic batched TN SGEMM (64x64x16) for small shapes ----------------
__global__ void __launch_bounds__(256) k_sgemm(
    const float* __restrict__ A, int lda, long sA,
    const float* __restrict__ Bw, int ldb, long sB,
    const float* __restrict__ bias,
    float* __restrict__ C, int ldc, long sC,
    int M, int N, int K)
{
    A  += (long)blockIdx.z * sA;
    Bw += (long)blockIdx.z * sB;
    C  += (long)blockIdx.z * sC;
    __shared__ float As[16][68];
    __shared__ float Bs[16][68];
    int tid = threadIdx.x;
    int tx = tid & 15, ty = tid >> 4;
    int row0 = blockIdx.y * 64, col0 = blockIdx.x * 64;
    int lm = tid >> 2, lk = (tid & 3) << 2;
    float acc[4][4] = {{0.f}};

    for (int k0 = 0; k0 < K; k0 += 16) {
        float4 va = make_float4(0.f, 0.f, 0.f, 0.f);
        float4 vb = make_float4(0.f, 0.f, 0.f, 0.f);
        if (row0 + lm < M) va = *(const float4*)(A + (long)(row0 + lm) * lda + k0 + lk);
        if (col0 + lm < N) vb = *(const float4*)(Bw + (long)(col0 + lm) * ldb + k0 + lk);
        __syncthreads();
        As[lk][lm] = va.x; As[lk+1][lm] = va.y; As[lk+2][lm] = va.z; As[lk+3][lm] = va.w;
        Bs[lk][lm] = vb.x; Bs[lk+1][lm] = vb.y; Bs[lk+2][lm] = vb.z; Bs[lk+3][lm] = vb.w;
        __syncthreads();
#pragma unroll
        for (int kk = 0; kk < 16; kk++) {
            float4 a = *(const float4*)&As[kk][ty << 2];
            float4 b = *(const float4*)&Bs[kk][tx << 2];
            acc[0][0] += a.x*b.x; acc[0][1] += a.x*b.y; acc[0][2] += a.x*b.z; acc[0][3] += a.x*b.w;
            acc[1][0] += a.y*b.x; acc[1][1] += a.y*b.y; acc[1][2] += a.y*b.z; acc[1][3] += a.y*b.w;
            acc[2][0] += a.z*b.x; acc[2][1] += a.z*b.y; acc[2][2] += a.z*b.z; acc[2][3] += a.z*b.w;
            acc[3][0] += a.w*b.x; acc[3][1] += a.w*b.y; acc[3][2] += a.w*b.z; acc[3][3] += a.w*b.w;
        }
    }
#pragma unroll
    for (int i = 0; i < 4; i++) {
        int gm = row0 + (ty << 2) + i;
        if (gm >= M) continue;
#pragma unroll
        for (int j = 0; j < 4; j++) {
            int gn = col0 + (tx << 2) + j;
            if (gn >= N) continue;
            float v = acc[i][j];
            if (bias) v += __ldg(&bias[gn]);
            C[(long)gm * ldc + gn] = v;
        }
    }
}

// ---------------- persistent bi-GRU encoder ----------------
// 100 blocks, 384 threads. Per-direction spin barrier (50 participants each).
__global__ void __launch_bounds__(384, 1) k_enc(
    const float* __restrict__ Whh_f, const float* __restrict__ Whh_b,
    const float* __restrict__ bhh_f, const float* __restrict__ bhh_b)
{
    extern __shared__ float sm[];
    float* Wt  = sm;                   // 24*400 = 9600
    float* hs  = sm + 9600;            // 16*404 = 6464
    float* ghs = sm + 9600 + 6464;     // 24*16  = 384
    float* bsh = ghs + 384;            // 24

    int dir = (int)(blockIdx.x / 50);
    int jb  = (int)(blockIdx.x % 50);
    int j0  = jb * 8;
    const float* Whh = dir ? Whh_b : Whh_f;
    const float* bhh = dir ? bhh_b : bhh_f;
    const float* GI  = d_S + (dir ? OGI1 : OGI0);
    float* OUT = d_S + (dir ? OHB : OHF);
    int tid = threadIdx.x;

    for (int i = tid; i < 24 * 400; i += 384) {
        int q = i / 400, k = i % 400;
        int gate = q >> 3, jl = q & 7;
        Wt[i] = Whh[(long)(gate * 400 + j0 + jl) * 400 + k];
    }
    if (tid < 24) { int gate = tid >> 3, jl = tid & 7; bsh[tid] = bhh[gate * 400 + j0 + jl]; }
    __syncthreads();

    int q = tid >> 4, r = tid & 15;
    const float* Wrow = Wt + q * 400;

    for (int t = 0; t < TENC; ++t) {
        int p = t & 1;
        const float4* Hin4 = (const float4*)d_Hbuf[dir][p];
        float* Hout = d_Hbuf[dir][p ^ 1];

        // stage h into smem (L2 loads: bypass possibly-stale L1)
        for (int i4 = tid; i4 < 1600; i4 += 384) {
            float4 v = __ldcg(Hin4 + i4);
            int row = i4 / 100, c4 = (i4 % 100) << 2;
            *(float4*)&hs[row * 404 + c4] = v;
        }
        __syncthreads();

        float a0 = 0.f, a1 = 0.f, a2 = 0.f, a3 = 0.f;
        const float* hrow = hs + r * 404;
#pragma unroll 4
        for (int k = 0; k < 400; k += 4) {
            float4 hv = *(const float4*)(hrow + k);
            float4 wv = *(const float4*)(Wrow + k);
            a0 += hv.x * wv.x; a1 += hv.y * wv.y; a2 += hv.z * wv.z; a3 += hv.w * wv.w;
        }
        ghs[q * 16 + r] = (a0 + a1) + (a2 + a3) + bsh[q];
        __syncthreads();

        if (tid < 128) {
            int rr = tid & 15, jj = tid >> 4;   // jj 0..7
            int time = dir ? (TENC - 1 - t) : t;
            long gib = ((long)time * Bb + rr) * H3 + j0 + jj;
            float ir = GI[gib], iz = GI[gib + 400], ig = GI[gib + 800];
            float hr_ = ghs[jj * 16 + rr];
            float hz_ = ghs[(8 + jj) * 16 + rr];
            float hg_ = ghs[(16 + jj) * 16 + rr];
            float hp  = hs[rr * 404 + j0 + jj];
            float rg = fsig(ir + hr_);
            float zg = fsig(iz + hz_);
            float gg = tanhf(ig + rg * hg_);
            float hn = (1.f - zg) * gg + zg * hp;
            Hout[rr * 400 + j0 + jj] = hn;
            OUT[((long)time * Bb + rr) * Hh + j0 + jj] = hn;
        }
        __threadfence();
        __syncthreads();
        if (tid == 0) {
            unsigned a = atomicAdd(&g_barcnt[dir], 1u);
            if (a == 50u * (unsigned)(t + 1) - 1u) {
                __threadfence();
                atomicAdd(&g_bargen[dir], 1u);
            } else {
                while (__ldcg((const unsigned*)&g_bargen[dir]) < (unsigned)(t + 1)) { __nanosleep(32); }
            }
            __threadfence();
        }
        __syncthreads();
    }
}

// ---------------- enc_out (B,T,H) and its transpose (B,H,T) ----------------
__global__ void k_encout() {
    long idx = (long)blockIdx.x * blockDim.x + threadIdx.x;
    if (idx >= (long)Bb * TENC * Hh) return;
    int b = (int)(idx / (TENC * Hh));
    int rem = (int)(idx % (TENC * Hh));
    int t = rem / Hh, h = rem % Hh;
    long src = ((long)t * Bb + b) * Hh + h;
    float v = d_S[OHF + src] + d_S[OHB + src];
    d_S[OEO + idx] = v;
    d_S[OEOT + (long)b * (Hh * TENC) + (long)h * TENC + t] = v;
}

// ---------------- decoder init: h = enc_hidden[b], din = slot_emb[s] ----------------
__global__ void k_dec_init(const float* __restrict__ slot) {
    int idx = blockIdx.x * blockDim.x + threadIdx.x;
    if (idx >= SB * Hh) return;
    int n = idx / Hh, h = idx % Hh;
    int s = n >> 4, b = n & 15;
    d_S[OH + idx]   = d_S[OHF + ((long)(TENC - 1) * Bb + b) * Hh + h]
                    + d_S[OHB + ((long)b) * Hh + h];
    d_S[ODIN + idx] = slot[s * Hh + h];
}

// ---------------- decoder GRU gates (in-place update of h); also zero rowsum ----------------
__global__ void k_dec_gates() {
    int idx = blockIdx.x * blockDim.x + threadIdx.x;
    if (idx < SB) d_S[ORSUM + idx] = 0.f;
    if (idx >= SB * Hh) return;
    int n = idx / Hh, j = idx % Hh;
    long gb = (long)n * H3 + j;
    float ir = d_S[OGI + gb], iz = d_S[OGI + gb + 400], ig = d_S[OGI + gb + 800];
    float hr = d_S[OGH + gb], hz = d_S[OGH + gb + 400], hg = d_S[OGH + gb + 800];
    float hp = d_S[OH + idx];
    float r = fsig(ir + hr);
    float z = fsig(iz + hz);
    float g = tanhf(ig + r * hg);
    d_S[OH + idx] = (1.f - z) * g + z * hp;
}

// ---------------- attention softmax over T=256 ----------------
__global__ void k_softmax_att() {
    int n = blockIdx.x, tid = threadIdx.x;
    __shared__ float red[256];
    float x = d_S[OPROB + (long)n * TENC + tid];
    red[tid] = x; __syncthreads();
    for (int o = 128; o; o >>= 1) { if (tid < o) red[tid] = fmaxf(red[tid], red[tid + o]); __syncthreads(); }
    float m = red[0]; __syncthreads();
    float e = fexp(x - m);
    red[tid] = e; __syncthreads();
    for (int o = 128; o; o >>= 1) { if (tid < o) red[tid] += red[tid + o]; __syncthreads(); }
    d_S[OPROB + (long)n * TENC + tid] = e / red[0];
}

// ---------------- sw (p_gen ratio) and (t==0) gate outputs ----------------
__global__ void k_sw_gate(const float* __restrict__ Wr, const float* __restrict__ br,
                          const float* __restrict__ Wg, const float* __restrict__ bg,
                          float* __restrict__ out, int t) {
    int warp = (blockIdx.x * blockDim.x + threadIdx.x) >> 5;
    int lane = threadIdx.x & 31;
    if (warp >= SB) return;
    int n = warp;
    float s = 0.f;
    for (int j = lane; j < H3; j += 32) {
        float v = (j < 400) ? d_S[OH + (long)n * Hh + j]
                : (j < 800) ? d_S[OCTX + (long)n * Hh + j - 400]
                            : d_S[ODIN + (long)n * Hh + j - 800];
        s += v * Wr[j];
    }
    for (int o = 16; o; o >>= 1) s += __shfl_xor_sync(0xffffffffu, s, o);
    if (lane == 0) d_S[OSW + n] = fsig(s + br[0]);
    if (t == 0) {
        for (int g = 0; g < Gg; g++) {
            float a = 0.f;
            for (int j = lane; j < Hh; j += 32) a += d_S[OCTX + (long)n * Hh + j] * Wg[g * Hh + j];
            for (int o = 16; o; o >>= 1) a += __shfl_xor_sync(0xffffffffu, a, o);
            if (lane == 0) out[PTR_OUT + (long)n * Gg + g] = a + bg[g];
        }
    }
}

// ---------------- write sw * p_vocab = sw * exp(l) / rowsum ----------------
__global__ void k_final(float* __restrict__ out, int t) {
    long idx = (long)blockIdx.x * blockDim.x + threadIdx.x;   // float4 index
    if (idx >= (long)SB * (Vv / 4)) return;
    int n = (int)(idx / (Vv / 4));
    int c = (int)(idx % (Vv / 4)) * 4;
    float4 l = *(const float4*)(d_S + OLOG + (long)n * Vv + c);
    float sc = d_S[OSW + n] / d_S[ORSUM + n];
    float4 o;
    o.x = fexp(l.x) * sc;
    o.y = fexp(l.y) * sc;
    o.z = fexp(l.z) * sc;
    o.w = fexp(l.w) * sc;
    *(float4*)(out + ((long)n * TDEC + t) * Vv + c) = o;
}

// ---------------- scatter-add pointer distribution ----------------
__global__ void k_scatter(float* __restrict__ out, const int* __restrict__ story, int t) {
    int idx = blockIdx.x * blockDim.x + threadIdx.x;
    if (idx >= SB * TENC) return;
    int n = idx >> 8, tt = idx & 255;
    int b = n & 15;
    int tok = story[b * TENC + tt];
    float v = (1.f - d_S[OSW + n]) * d_S[OPROB + (long)n * TENC + tt];
    atomicAdd(out + ((long)n * TDEC + t) * Vv + tok, v);
}

// ---------------- next decoder input: emb[tf_tokens[t]] ----------------
__global__ void k_next_din(const int* __restrict__ tb, const float* __restrict__ emb, int t) {
    int idx = blockIdx.x * blockDim.x + threadIdx.x;
    if (idx >= SB * Hh) return;
    int n = idx / Hh, h = idx % Hh;
    int s = n >> 4, b = n & 15;
    int tok = tb[(b * Ss + s) * TDEC + t];
    d_S[ODIN + idx] = emb[(long)tok * Hh + h];
}

// ---------------- host ----------------
extern "C" void kernel_launch(void* const* d_in, const int* in_sizes, int n_in,
                              void* d_out, int out_size) {
    const int*   story = (const int*)d_in[0];
    const int*   tb    = (const int*)d_in[1];
    const float* emb   = (const float*)d_in[2];
    const float* eWif  = (const float*)d_in[3];
    const float* eWhf  = (const float*)d_in[4];
    const float* ebif  = (const float*)d_in[5];
    const float* ebhf  = (const float*)d_in[6];
    const float* eWib  = (const float*)d_in[7];
    const float* eWhb  = (const float*)d_in[8];
    const float* ebib  = (const float*)d_in[9];
    const float* ebhb  = (const float*)d_in[10];
    const float* dWi   = (const float*)d_in[11];
    const float* dWh   = (const float*)d_in[12];
    const float* dbi   = (const float*)d_in[13];
    const float* dbh   = (const float*)d_in[14];
    const float* Wr    = (const float*)d_in[15];
    const float* br    = (const float*)d_in[16];
    const float* Wg    = (const float*)d_in[17];
    const float* bg    = (const float*)d_in[18];
    const float* slot  = (const float*)d_in[19];
    float* out = (float*)d_out;

    cudaFuncSetAttribute(k_enc, cudaFuncAttributeMaxDynamicSharedMemorySize, 66000);

    float* S = nullptr;
    cudaGetSymbolAddress((void**)&S, d_S);
    float* pX    = S + OX;
    float* pGI0  = S + OGI0;
    float* pGI1  = S + OGI1;
    float* pEO   = S + OEO;
    float* pEOT  = S + OEOT;
    float* pH    = S + OH;
    float* pDIN  = S + ODIN;
    float* pGI   = S + OGI;
    float* pGH   = S + OGH;
    float* pPROB = S + OPROB;
    float* pCTX  = S + OCTX;
    float* pRS   = S + ORSUM;
    float* pLOG  = S + OLOG;

    k_init<<<32, 256>>>();
    k_embed<<<(TENC * Bb * Hh + 255) / 256, 256>>>(story, emb);

    // GI (input gates) for both encoder directions: (4096 x 1200 x 400)
    k_gemm128<<<dim3(10, 32), 256>>>(pX, Hh, eWif, Hh, ebif, pGI0, H3, nullptr, TENC * Bb, H3, Hh);
    k_gemm128<<<dim3(10, 32), 256>>>(pX, Hh, eWib, Hh, ebib, pGI1, H3, nullptr, TENC * Bb, H3, Hh);

    // persistent bidirectional GRU
    k_enc<<<100, 384, 66000>>>(eWhf, eWhb, ebhf, ebhb);

    k_encout<<<(Bb * TENC * Hh + 255) / 256, 256>>>();
    k_dec_init<<<(SB * Hh + 255) / 256, 256>>>(slot);

    for (int t = 0; t < TDEC; t++) {
        // GRU: gi = din@Wih^T+bih ; gh = h@Whh^T+bhh ; gates (+ zero rowsum)
        k_sgemm<<<dim3(19, 8, 1), 256>>>(pDIN, Hh, 0, dWi, Hh, 0, dbi, pGI, H3, 0, SB, H3, Hh);
        k_sgemm<<<dim3(19, 8, 1), 256>>>(pH,   Hh, 0, dWh, Hh, 0, dbh, pGH, H3, 0, SB, H3, Hh);
        k_dec_gates<<<(SB * Hh + 255) / 256, 256>>>();

        // attention: scores (batched over b), softmax, context (batched over b)
        k_sgemm<<<dim3(4, 1, Bb), 256>>>(pH, Bb * Hh, Hh, pEO, Hh, (long)TENC * Hh,
                                         nullptr, pPROB, Bb * TENC, TENC, Ss, TENC, Hh);
        k_softmax_att<<<SB, 256>>>();
        k_sgemm<<<dim3(7, 1, Bb), 256>>>(pPROB, Bb * TENC, TENC, pEOT, TENC, (long)Hh * TENC,
                                         nullptr, pCTX, Bb * Hh, Hh, Ss, Hh, TENC);

        k_sw_gate<<<60, 256>>>(Wr, br, Wg, bg, out, t);

        // vocab logits + fused row-sum-of-exp epilogue
        k_gemm128<<<dim3(141, 4), 256>>>(pH, Hh, emb, Hh, nullptr, pLOG, Vv, pRS, SB, Vv, Hh);
        k_final<<<(SB * (Vv / 4) + 255) / 256, 256>>>(out, t);
        k_scatter<<<SB, 256>>>(out, story, t);

        k_next_din<<<(SB * Hh + 255) / 256, 256>>>(tb, emb, t);
    }
}

// round 6
// speedup vs baseline: 1.1906x; 1.0662x over previous
#include <cuda_runtime.h>
#include <math.h>

#define Vv 18000
#define Hh 400
#define Bb 16
#define TENC 256
#define Ss 30
#define TDEC 8
#define Gg 3
#define SB 480
#define H3 1200
#define PTR_OUT 69120000L

typedef unsigned long long ull;

// ---------------- scratch: one big __device__ array + offsets ----------------
#define OX    0L
#define OGI0  1638400L
#define OGI1  6553600L
#define OHF   11468800L
#define OHB   13107200L
#define OEO   14745600L
#define OEOT  16384000L
#define OH    18022400L
#define ODIN  18214400L
#define OGI   18406400L
#define OGH   18982400L
#define OPROB 19558400L
#define OCTX  19681280L
#define OSW   19873280L
#define ORSUM 19873760L
#define OLOG  19874720L
#define STOT  28514720L

__device__ float d_S[STOT];
__device__ float d_Hbuf[2][2][Bb * Hh];   // [dir][parity][16*400]
__device__ unsigned g_barcnt[2], g_bargen[2];

// ---------------- packed f32x2 helpers (Blackwell FFMA2) ----------------
__device__ __forceinline__ ull pack2(float x, float y) {
    ull r; asm("mov.b64 %0, {%1, %2};" : "=l"(r) : "f"(x), "f"(y)); return r;
}
__device__ __forceinline__ void unpack2(ull v, float& x, float& y) {
    asm("mov.b64 {%0, %1}, %2;" : "=f"(x), "=f"(y) : "l"(v));
}
__device__ __forceinline__ void ffma2(ull& d, ull a, ull b) {
    asm("fma.rn.f32x2 %0, %1, %2, %3;" : "=l"(d) : "l"(a), "l"(b), "l"(d));
}

// ---------------- fast exp (FMA-only, rel err ~1e-7) ----------------
__device__ __forceinline__ float fexp(float x) {
    x = fminf(fmaxf(x, -80.0f), 80.0f);
    float y = x * 1.4426950408889634f;
    int   i = __float2int_rn(y);
    float f = y - (float)i;
    float u = f * 0.6931471805599453f;
    float p = 1.0f + u * (1.0f + u * (0.5f + u * (0.16666667f +
              u * (0.041666668f + u * (0.008333334f + u * 0.0013888889f)))));
    return __int_as_float(__float_as_int(p) + (i << 23));
}
__device__ __forceinline__ float fsig(float x) { return 1.0f / (1.0f + fexp(-x)); }

// ---------------- init ----------------
__global__ void k_init() {
    int tid = blockIdx.x * blockDim.x + threadIdx.x;
    if (tid == 0) {
        g_barcnt[0] = 0u; g_barcnt[1] = 0u;
        g_bargen[0] = 0u; g_bargen[1] = 0u;
    }
    for (int i = tid; i < 2 * 2 * Bb * Hh; i += gridDim.x * blockDim.x)
        ((float*)d_Hbuf)[i] = 0.0f;
}

// ---------------- embed story: d_X[t][b][h] ----------------
__global__ void k_embed(const int* __restrict__ story, const float* __restrict__ emb) {
    long idx = (long)blockIdx.x * blockDim.x + threadIdx.x;
    if (idx >= (long)TENC * Bb * Hh) return;
    int h = (int)(idx % Hh);
    int tb = (int)(idx / Hh);
    int b = tb & 15, t = tb >> 4;
    d_S[OX + idx] = emb[(long)story[b * TENC + t] * Hh + h];
}

// ---------------- 128x128x8 double-buffered TN SGEMM (FFMA2 core) ----------------
// C = A[M,K] @ Bw[N,K]^T (+bias). Optional epilogue: rowsum[gm] += sum_j fexp(C[gm][j]).
__global__ void __launch_bounds__(256) k_gemm128(
    const float* __restrict__ A, int lda,
    const float* __restrict__ Bw, int ldb,
    const float* __restrict__ bias,
    float* __restrict__ C, int ldc,
    float* __restrict__ rowsum,
    int M, int N, int K)
{
    __shared__ float As[2][8][132];
    __shared__ float Bs[2][8][132];
    int tid = threadIdx.x;
    int tx = tid & 15, ty = tid >> 4;
    int row0 = blockIdx.y * 128, col0 = blockIdx.x * 128;
    int lm = tid >> 1, lk = (tid & 1) << 2;

    bool av = (row0 + lm) < M;
    bool bv = (col0 + lm) < N;
    const float* Ap = A + (long)(row0 + lm) * lda + lk;
    const float* Bp = Bw + (long)(col0 + lm) * ldb + lk;
    const float4 z4 = make_float4(0.f, 0.f, 0.f, 0.f);

    float4 va = av ? *(const float4*)Ap : z4;
    float4 vb = bv ? *(const float4*)Bp : z4;
    As[0][lk + 0][lm] = va.x; As[0][lk + 1][lm] = va.y; As[0][lk + 2][lm] = va.z; As[0][lk + 3][lm] = va.w;
    Bs[0][lk + 0][lm] = vb.x; Bs[0][lk + 1][lm] = vb.y; Bs[0][lk + 2][lm] = vb.z; Bs[0][lk + 3][lm] = vb.w;
    __syncthreads();

    ull acc[8][4];
#pragma unroll
    for (int i = 0; i < 8; i++)
#pragma unroll
        for (int p = 0; p < 4; p++) acc[i][p] = 0ULL;

    int KT = K >> 3;
    for (int kt = 0; kt < KT; kt++) {
        int bf = kt & 1;
        float4 nva, nvb;
        if (kt + 1 < KT) {
            nva = av ? *(const float4*)(Ap + (kt + 1) * 8) : z4;
            nvb = bv ? *(const float4*)(Bp + (kt + 1) * 8) : z4;
        }
#pragma unroll
        for (int kk = 0; kk < 8; kk++) {
            float a[8], b[8];
            *(float4*)(a)     = *(const float4*)&As[bf][kk][ty << 2];
            *(float4*)(a + 4) = *(const float4*)&As[bf][kk][64 + (ty << 2)];
            *(float4*)(b)     = *(const float4*)&Bs[bf][kk][tx << 2];
            *(float4*)(b + 4) = *(const float4*)&Bs[bf][kk][64 + (tx << 2)];
            ull bp[4];
            bp[0] = pack2(b[0], b[1]); bp[1] = pack2(b[2], b[3]);
            bp[2] = pack2(b[4], b[5]); bp[3] = pack2(b[6], b[7]);
#pragma unroll
            for (int i = 0; i < 8; i++) {
                ull ad = pack2(a[i], a[i]);
                ffma2(acc[i][0], ad, bp[0]);
                ffma2(acc[i][1], ad, bp[1]);
                ffma2(acc[i][2], ad, bp[2]);
                ffma2(acc[i][3], ad, bp[3]);
            }
        }
        if (kt + 1 < KT) {
            int nb = bf ^ 1;
            As[nb][lk + 0][lm] = nva.x; As[nb][lk + 1][lm] = nva.y; As[nb][lk + 2][lm] = nva.z; As[nb][lk + 3][lm] = nva.w;
            Bs[nb][lk + 0][lm] = nvb.x; Bs[nb][lk + 1][lm] = nvb.y; Bs[nb][lk + 2][lm] = nvb.z; Bs[nb][lk + 3][lm] = nvb.w;
            __syncthreads();
        }
    }

#pragma unroll
    for (int i = 0; i < 8; i++) {
        int gm = row0 + ((i < 4) ? (ty << 2) + i : 64 + (ty << 2) + i - 4);
        bool rv = gm < M;
        float s = 0.f;
#pragma unroll
        for (int p = 0; p < 4; p++) {
            float v0, v1;
            unpack2(acc[i][p], v0, v1);
            int j0i = 2 * p;                       // j index of v0 within 0..7
            int gn0 = col0 + ((j0i < 4) ? (tx << 2) + j0i : 64 + (tx << 2) + j0i - 4);
            int gn1 = gn0 + 1;
            if (gn0 < N) {
                float v = v0 + (bias ? __ldg(&bias[gn0]) : 0.f);
                if (rv) C[(long)gm * ldc + gn0] = v;
                if (rowsum) s += fexp(v);
            }
            if (gn1 < N) {
                float v = v1 + (bias ? __ldg(&bias[gn1]) : 0.f);
                if (rv) C[(long)gm * ldc + gn1] = v;
                if (rowsum) s += fexp(v);
            }
        }
        if (rowsum) {
#pragma unroll
            for (int o = 8; o; o >>= 1) s += __shfl_xor_sync(0xffffffffu, s, o);
            if (tx == 0 && rv) atomicAdd(rowsum + gm, s);
        }
    }
}

// ---------------- generic batched TN SGEMM (64x64x16, FFMA2 core) ----------------
__global__ void __launch_bounds__(256) k_sgemm(
    const float* __restrict__ A, int lda, long sA,
    const float* __restrict__ Bw, int ldb, long sB,
    const float* __restrict__ bias,
    float* __restrict__ C, int ldc, long sC,
    int M, int N, int K)
{
    A  += (long)blockIdx.z * sA;
    Bw += (long)blockIdx.z * sB;
    C  += (long)blockIdx.z * sC;
    __shared__ float As[16][68];
    __shared__ float Bs[16][68];
    int tid = threadIdx.x;
    int tx = tid & 15, ty = tid >> 4;
    int row0 = blockIdx.y * 64, col0 = blockIdx.x * 64;
    int lm = tid >> 2, lk = (tid & 3) << 2;
    ull acc[4][2];
#pragma unroll
    for (int i = 0; i < 4; i++) { acc[i][0] = 0ULL; acc[i][1] = 0ULL; }

    for (int k0 = 0; k0 < K; k0 += 16) {
        float4 va = make_float4(0.f, 0.f, 0.f, 0.f);
        float4 vb = make_float4(0.f, 0.f, 0.f, 0.f);
        if (row0 + lm < M) va = *(const float4*)(A + (long)(row0 + lm) * lda + k0 + lk);
        if (col0 + lm < N) vb = *(const float4*)(Bw + (long)(col0 + lm) * ldb + k0 + lk);
        __syncthreads();
        As[lk][lm] = va.x; As[lk+1][lm] = va.y; As[lk+2][lm] = va.z; As[lk+3][lm] = va.w;
        Bs[lk][lm] = vb.x; Bs[lk+1][lm] = vb.y; Bs[lk+2][lm] = vb.z; Bs[lk+3][lm] = vb.w;
        __syncthreads();
#pragma unroll
        for (int kk = 0; kk < 16; kk++) {
            float4 a = *(const float4*)&As[kk][ty << 2];
            float4 b = *(const float4*)&Bs[kk][tx << 2];
            ull b01 = pack2(b.x, b.y), b23 = pack2(b.z, b.w);
            ull ad;
            ad = pack2(a.x, a.x); ffma2(acc[0][0], ad, b01); ffma2(acc[0][1], ad, b23);
            ad = pack2(a.y, a.y); ffma2(acc[1][0], ad, b01); ffma2(acc[1][1], ad, b23);
            ad = pack2(a.z, a.z); ffma2(acc[2][0], ad, b01); ffma2(acc[2][1], ad, b23);
            ad = pack2(a.w, a.w); ffma2(acc[3][0], ad, b01); ffma2(acc[3][1], ad, b23);
        }
    }
#pragma unroll
    for (int i = 0; i < 4; i++) {
        int gm = row0 + (ty << 2) + i;
        if (gm >= M) continue;
        float v[4];
        unpack2(acc[i][0], v[0], v[1]);
        unpack2(acc[i][1], v[2], v[3]);
#pragma unroll
        for (int j = 0; j < 4; j++) {
            int gn = col0 + (tx << 2) + j;
            if (gn >= N) continue;
            float w = v[j];
            if (bias) w += __ldg(&bias[gn]);
            C[(long)gm * ldc + gn] = w;
        }
    }
}

// ---------------- persistent bi-GRU encoder ----------------
// 100 blocks, 384 threads. Per-direction spin barrier (50 participants each).
__global__ void __launch_bounds__(384, 1) k_enc(
    const float* __restrict__ Whh_f, const float* __restrict__ Whh_b,
    const float* __restrict__ bhh_f, const float* __restrict__ bhh_b)
{
    extern __shared__ float sm[];
    float* Wt  = sm;                   // 24*400 = 9600
    float* hs  = sm + 9600;            // 16*404 = 6464
    float* ghs = sm + 9600 + 6464;     // 24*16  = 384
    float* bsh = ghs + 384;            // 24

    int dir = (int)(blockIdx.x / 50);
    int jb  = (int)(blockIdx.x % 50);
    int j0  = jb * 8;
    const float* Whh = dir ? Whh_b : Whh_f;
    const float* bhh = dir ? bhh_b : bhh_f;
    const float* GI  = d_S + (dir ? OGI1 : OGI0);
    float* OUT = d_S + (dir ? OHB : OHF);
    int tid = threadIdx.x;

    for (int i = tid; i < 24 * 400; i += 384) {
        int q = i / 400, k = i % 400;
        int gate = q >> 3, jl = q & 7;
        Wt[i] = Whh[(long)(gate * 400 + j0 + jl) * 400 + k];
    }
    if (tid < 24) { int gate = tid >> 3, jl = tid & 7; bsh[tid] = bhh[gate * 400 + j0 + jl]; }
    __syncthreads();

    int q = tid >> 4, r = tid & 15;
    const float* Wrow = Wt + q * 400;

    for (int t = 0; t < TENC; ++t) {
        int p = t & 1;
        const float4* Hin4 = (const float4*)d_Hbuf[dir][p];
        float* Hout = d_Hbuf[dir][p ^ 1];

        // stage h into smem (L2 loads: bypass possibly-stale L1)
        for (int i4 = tid; i4 < 1600; i4 += 384) {
            float4 v = __ldcg(Hin4 + i4);
            int row = i4 / 100, c4 = (i4 % 100) << 2;
            *(float4*)&hs[row * 404 + c4] = v;
        }
        __syncthreads();

        float a0 = 0.f, a1 = 0.f, a2 = 0.f, a3 = 0.f;
        const float* hrow = hs + r * 404;
#pragma unroll 4
        for (int k = 0; k < 400; k += 4) {
            float4 hv = *(const float4*)(hrow + k);
            float4 wv = *(const float4*)(Wrow + k);
            a0 += hv.x * wv.x; a1 += hv.y * wv.y; a2 += hv.z * wv.z; a3 += hv.w * wv.w;
        }
        ghs[q * 16 + r] = (a0 + a1) + (a2 + a3) + bsh[q];
        __syncthreads();

        if (tid < 128) {
            int rr = tid & 15, jj = tid >> 4;   // jj 0..7
            int time = dir ? (TENC - 1 - t) : t;
            long gib = ((long)time * Bb + rr) * H3 + j0 + jj;
            float ir = GI[gib], iz = GI[gib + 400], ig = GI[gib + 800];
            float hr_ = ghs[jj * 16 + rr];
            float hz_ = ghs[(8 + jj) * 16 + rr];
            float hg_ = ghs[(16 + jj) * 16 + rr];
            float hp  = hs[rr * 404 + j0 + jj];
            float rg = fsig(ir + hr_);
            float zg = fsig(iz + hz_);
            float gg = tanhf(ig + rg * hg_);
            float hn = (1.f - zg) * gg + zg * hp;
            Hout[rr * 400 + j0 + jj] = hn;
            OUT[((long)time * Bb + rr) * Hh + j0 + jj] = hn;
        }
        __syncthreads();                 // all h-stores of this block done
        if (tid == 0) {
            __threadfence();             // release (tid0 only; cumulative via bar)
            unsigned a = atomicAdd(&g_barcnt[dir], 1u);
            if (a == 50u * (unsigned)(t + 1) - 1u) {
                atomicAdd(&g_bargen[dir], 1u);
            } else {
                while (__ldcg((const unsigned*)&g_bargen[dir]) < (unsigned)(t + 1)) { __nanosleep(32); }
            }
            __threadfence();             // acquire
        }
        __syncthreads();
    }
}

// ---------------- enc_out (B,T,H) and its transpose (B,H,T) ----------------
__global__ void k_encout() {
    long idx = (long)blockIdx.x * blockDim.x + threadIdx.x;
    if (idx >= (long)Bb * TENC * Hh) return;
    int b = (int)(idx / (TENC * Hh));
    int rem = (int)(idx % (TENC * Hh));
    int t = rem / Hh, h = rem % Hh;
    long src = ((long)t * Bb + b) * Hh + h;
    float v = d_S[OHF + src] + d_S[OHB + src];
    d_S[OEO + idx] = v;
    d_S[OEOT + (long)b * (Hh * TENC) + (long)h * TENC + t] = v;
}

// ---------------- decoder init: h = enc_hidden[b], din = slot_emb[s] ----------------
__global__ void k_dec_init(const float* __restrict__ slot) {
    int idx = blockIdx.x * blockDim.x + threadIdx.x;
    if (idx >= SB * Hh) return;
    int n = idx / Hh, h = idx % Hh;
    int s = n >> 4, b = n & 15;
    d_S[OH + idx]   = d_S[OHF + ((long)(TENC - 1) * Bb + b) * Hh + h]
                    + d_S[OHB + ((long)b) * Hh + h];
    d_S[ODIN + idx] = slot[s * Hh + h];
}

// ---------------- decoder GRU gates (in-place update of h); also zero rowsum ----------------
__global__ void k_dec_gates() {
    int idx = blockIdx.x * blockDim.x + threadIdx.x;
    if (idx < SB) d_S[ORSUM + idx] = 0.f;
    if (idx >= SB * Hh) return;
    int n = idx / Hh, j = idx % Hh;
    long gb = (long)n * H3 + j;
    float ir = d_S[OGI + gb], iz = d_S[OGI + gb + 400], ig = d_S[OGI + gb + 800];
    float hr = d_S[OGH + gb], hz = d_S[OGH + gb + 400], hg = d_S[OGH + gb + 800];
    float hp = d_S[OH + idx];
    float r = fsig(ir + hr);
    float z = fsig(iz + hz);
    float g = tanhf(ig + r * hg);
    d_S[OH + idx] = (1.f - z) * g + z * hp;
}

// ---------------- attention softmax over T=256 ----------------
__global__ void k_softmax_att() {
    int n = blockIdx.x, tid = threadIdx.x;
    __shared__ float red[256];
    float x = d_S[OPROB + (long)n * TENC + tid];
    red[tid] = x; __syncthreads();
    for (int o = 128; o; o >>= 1) { if (tid < o) red[tid] = fmaxf(red[tid], red[tid + o]); __syncthreads(); }
    float m = red[0]; __syncthreads();
    float e = fexp(x - m);
    red[tid] = e; __syncthreads();
    for (int o = 128; o; o >>= 1) { if (tid < o) red[tid] += red[tid + o]; __syncthreads(); }
    d_S[OPROB + (long)n * TENC + tid] = e / red[0];
}

// ---------------- sw (p_gen ratio) and (t==0) gate outputs ----------------
__global__ void k_sw_gate(const float* __restrict__ Wr, const float* __restrict__ br,
                          const float* __restrict__ Wg, const float* __restrict__ bg,
                          float* __restrict__ out, int t) {
    int warp = (blockIdx.x * blockDim.x + threadIdx.x) >> 5;
    int lane = threadIdx.x & 31;
    if (warp >= SB) return;
    int n = warp;
    float s = 0.f;
    for (int j = lane; j < H3; j += 32) {
        float v = (j < 400) ? d_S[OH + (long)n * Hh + j]
                : (j < 800) ? d_S[OCTX + (long)n * Hh + j - 400]
                            : d_S[ODIN + (long)n * Hh + j - 800];
        s += v * Wr[j];
    }
    for (int o = 16; o; o >>= 1) s += __shfl_xor_sync(0xffffffffu, s, o);
    if (lane == 0) d_S[OSW + n] = fsig(s + br[0]);
    if (t == 0) {
        for (int g = 0; g < Gg; g++) {
            float a = 0.f;
            for (int j = lane; j < Hh; j += 32) a += d_S[OCTX + (long)n * Hh + j] * Wg[g * Hh + j];
            for (int o = 16; o; o >>= 1) a += __shfl_xor_sync(0xffffffffu, a, o);
            if (lane == 0) out[PTR_OUT + (long)n * Gg + g] = a + bg[g];
        }
    }
}

// ---------------- write sw * p_vocab = sw * exp(l) / rowsum ----------------
__global__ void k_final(float* __restrict__ out, int t) {
    long idx = (long)blockIdx.x * blockDim.x + threadIdx.x;   // float4 index
    if (idx >= (long)SB * (Vv / 4)) return;
    int n = (int)(idx / (Vv / 4));
    int c = (int)(idx % (Vv / 4)) * 4;
    float4 l = *(const float4*)(d_S + OLOG + (long)n * Vv + c);
    float sc = d_S[OSW + n] / d_S[ORSUM + n];
    float4 o;
    o.x = fexp(l.x) * sc;
    o.y = fexp(l.y) * sc;
    o.z = fexp(l.z) * sc;
    o.w = fexp(l.w) * sc;
    *(float4*)(out + ((long)n * TDEC + t) * Vv + c) = o;
}

// ---------------- scatter-add pointer distribution ----------------
__global__ void k_scatter(float* __restrict__ out, const int* __restrict__ story, int t) {
    int idx = blockIdx.x * blockDim.x + threadIdx.x;
    if (idx >= SB * TENC) return;
    int n = idx >> 8, tt = idx & 255;
    int b = n & 15;
    int tok = story[b * TENC + tt];
    float v = (1.f - d_S[OSW + n]) * d_S[OPROB + (long)n * TENC + tt];
    atomicAdd(out + ((long)n * TDEC + t) * Vv + tok, v);
}

// ---------------- next decoder input: emb[tf_tokens[t]] ----------------
__global__ void k_next_din(const int* __restrict__ tb, const float* __restrict__ emb, int t) {
    int idx = blockIdx.x * blockDim.x + threadIdx.x;
    if (idx >= SB * Hh) return;
    int n = idx / Hh, h = idx % Hh;
    int s = n >> 4, b = n & 15;
    int tok = tb[(b * Ss + s) * TDEC + t];
    d_S[ODIN + idx] = emb[(long)tok * Hh + h];
}

// ---------------- host ----------------
extern "C" void kernel_launch(void* const* d_in, const int* in_sizes, int n_in,
                              void* d_out, int out_size) {
    const int*   story = (const int*)d_in[0];
    const int*   tb    = (const int*)d_in[1];
    const float* emb   = (const float*)d_in[2];
    const float* eWif  = (const float*)d_in[3];
    const float* eWhf  = (const float*)d_in[4];
    const float* ebif  = (const float*)d_in[5];
    const float* ebhf  = (const float*)d_in[6];
    const float* eWib  = (const float*)d_in[7];
    const float* eWhb  = (const float*)d_in[8];
    const float* ebib  = (const float*)d_in[9];
    const float* ebhb  = (const float*)d_in[10];
    const float* dWi   = (const float*)d_in[11];
    const float* dWh   = (const float*)d_in[12];
    const float* dbi   = (const float*)d_in[13];
    const float* dbh   = (const float*)d_in[14];
    const float* Wr    = (const float*)d_in[15];
    const float* br    = (const float*)d_in[16];
    const float* Wg    = (const float*)d_in[17];
    const float* bg    = (const float*)d_in[18];
    const float* slot  = (const float*)d_in[19];
    float* out = (float*)d_out;

    cudaFuncSetAttribute(k_enc, cudaFuncAttributeMaxDynamicSharedMemorySize, 66000);

    float* S = nullptr;
    cudaGetSymbolAddress((void**)&S, d_S);
    float* pX    = S + OX;
    float* pGI0  = S + OGI0;
    float* pGI1  = S + OGI1;
    float* pEO   = S + OEO;
    float* pEOT  = S + OEOT;
    float* pH    = S + OH;
    float* pDIN  = S + ODIN;
    float* pGI   = S + OGI;
    float* pGH   = S + OGH;
    float* pPROB = S + OPROB;
    float* pCTX  = S + OCTX;
    float* pRS   = S + ORSUM;
    float* pLOG  = S + OLOG;

    k_init<<<32, 256>>>();
    k_embed<<<(TENC * Bb * Hh + 255) / 256, 256>>>(story, emb);

    // GI (input gates) for both encoder directions: (4096 x 1200 x 400)
    k_sgemm<<<dim3(19, 64, 1), 256>>>(pX, Hh, 0, eWif, Hh, 0, ebif, pGI0, H3, 0, TENC * Bb, H3, Hh);
    k_sgemm<<<dim3(19, 64, 1), 256>>>(pX, Hh, 0, eWib, Hh, 0, ebib, pGI1, H3, 0, TENC * Bb, H3, Hh);

    // persistent bidirectional GRU
    k_enc<<<100, 384, 66000>>>(eWhf, eWhb, ebhf, ebhb);

    k_encout<<<(Bb * TENC * Hh + 255) / 256, 256>>>();
    k_dec_init<<<(SB * Hh + 255) / 256, 256>>>(slot);

    for (int t = 0; t < TDEC; t++) {
        // GRU: gi = din@Wih^T+bih ; gh = h@Whh^T+bhh ; gates (+ zero rowsum)
        k_sgemm<<<dim3(19, 8, 1), 256>>>(pDIN, Hh, 0, dWi, Hh, 0, dbi, pGI, H3, 0, SB, H3, Hh);
        k_sgemm<<<dim3(19, 8, 1), 256>>>(pH,   Hh, 0, dWh, Hh, 0, dbh, pGH, H3, 0, SB, H3, Hh);
        k_dec_gates<<<(SB * Hh + 255) / 256, 256>>>();

        // attention: scores (batched over b), softmax, context (batched over b)
        k_sgemm<<<dim3(4, 1, Bb), 256>>>(pH, Bb * Hh, Hh, pEO, Hh, (long)TENC * Hh,
                                         nullptr, pPROB, Bb * TENC, TENC, Ss, TENC, Hh);
        k_softmax_att<<<SB, 256>>>();
        k_sgemm<<<dim3(7, 1, Bb), 256>>>(pPROB, Bb * TENC, TENC, pEOT, TENC, (long)Hh * TENC,
                                         nullptr, pCTX, Bb * Hh, Hh, Ss, Hh, TENC);

        k_sw_gate<<<60, 256>>>(Wr, br, Wg, bg, out, t);

        // vocab logits + fused row-sum-of-exp epilogue
        k_gemm128<<<dim3(141, 4), 256>>>(pH, Hh, emb, Hh, nullptr, pLOG, Vv, pRS, SB, Vv, Hh);
        k_final<<<(SB * (Vv / 4) + 255) / 256, 256>>>(out, t);
        k_scatter<<<SB, 256>>>(out, story, t);

        k_next_din<<<(SB * Hh + 255) / 256, 256>>>(tb, emb, t);
    }
}

// round 7
// speedup vs baseline: 1.3439x; 1.1287x over previous
#include <cuda_runtime.h>
#include <math.h>

#define Vv 18000
#define Hh 400
#define Bb 16
#define TENC 256
#define Ss 30
#define TDEC 8
#define Gg 3
#define SB 480
#define H3 1200
#define PTR_OUT 69120000L

typedef unsigned long long ull;

// ---------------- scratch: one big __device__ array + offsets ----------------
#define OX    0L
#define OGI0  1638400L
#define OGI1  6553600L
#define OHF   11468800L
#define OHB   13107200L
#define OEO   14745600L
#define OEOT  16384000L
#define OH    18022400L
#define ODIN  18214400L
#define OGI   18406400L
#define OGH   18982400L
#define OPROB 19558400L
#define OCTX  19681280L
#define OSW   19873280L
#define ORSUM 19873760L
#define OLOG  19874720L
#define STOT  28514720L

__device__ float d_S[STOT];
__device__ float d_Hbuf[2][2][Bb * Hh];   // [dir][parity][16*400]
__device__ unsigned g_barcnt[2], g_bargen[2];

// ---------------- packed f32x2 helpers (Blackwell FFMA2) ----------------
__device__ __forceinline__ ull pack2(float x, float y) {
    ull r; asm("mov.b64 %0, {%1, %2};" : "=l"(r) : "f"(x), "f"(y)); return r;
}
__device__ __forceinline__ void unpack2(ull v, float& x, float& y) {
    asm("mov.b64 {%0, %1}, %2;" : "=f"(x), "=f"(y) : "l"(v));
}
__device__ __forceinline__ void ffma2(ull& d, ull a, ull b) {
    asm("fma.rn.f32x2 %0, %1, %2, %3;" : "=l"(d) : "l"(a), "l"(b), "l"(d));
}

// ---------------- fast exp (FMA-only, rel err ~1e-7) ----------------
__device__ __forceinline__ float fexp(float x) {
    x = fminf(fmaxf(x, -80.0f), 80.0f);
    float y = x * 1.4426950408889634f;
    int   i = __float2int_rn(y);
    float f = y - (float)i;
    float u = f * 0.6931471805599453f;
    float p = 1.0f + u * (1.0f + u * (0.5f + u * (0.16666667f +
              u * (0.041666668f + u * (0.008333334f + u * 0.0013888889f)))));
    return __int_as_float(__float_as_int(p) + (i << 23));
}
__device__ __forceinline__ float fsig(float x) { return 1.0f / (1.0f + fexp(-x)); }

// ---------------- init ----------------
__global__ void k_init() {
    int tid = blockIdx.x * blockDim.x + threadIdx.x;
    if (tid == 0) {
        g_barcnt[0] = 0u; g_barcnt[1] = 0u;
        g_bargen[0] = 0u; g_bargen[1] = 0u;
    }
    for (int i = tid; i < 2 * 2 * Bb * Hh; i += gridDim.x * blockDim.x)
        ((float*)d_Hbuf)[i] = 0.0f;
}

// ---------------- embed story: d_X[t][b][h] ----------------
__global__ void k_embed(const int* __restrict__ story, const float* __restrict__ emb) {
    long idx = (long)blockIdx.x * blockDim.x + threadIdx.x;
    if (idx >= (long)TENC * Bb * Hh) return;
    int h = (int)(idx % Hh);
    int tb = (int)(idx / Hh);
    int b = tb & 15, t = tb >> 4;
    d_S[OX + idx] = emb[(long)story[b * TENC + t] * Hh + h];
}

// ---------------- 128x128x8 double-buffered TN SGEMM (FFMA2 core) ----------------
__global__ void __launch_bounds__(256) k_gemm128(
    const float* __restrict__ A, int lda,
    const float* __restrict__ Bw, int ldb,
    const float* __restrict__ bias,
    float* __restrict__ C, int ldc,
    float* __restrict__ rowsum,
    int M, int N, int K)
{
    __shared__ float As[2][8][132];
    __shared__ float Bs[2][8][132];
    int tid = threadIdx.x;
    int tx = tid & 15, ty = tid >> 4;
    int row0 = blockIdx.y * 128, col0 = blockIdx.x * 128;
    int lm = tid >> 1, lk = (tid & 1) << 2;

    bool av = (row0 + lm) < M;
    bool bv = (col0 + lm) < N;
    const float* Ap = A + (long)(row0 + lm) * lda + lk;
    const float* Bp = Bw + (long)(col0 + lm) * ldb + lk;
    const float4 z4 = make_float4(0.f, 0.f, 0.f, 0.f);

    float4 va = av ? *(const float4*)Ap : z4;
    float4 vb = bv ? *(const float4*)Bp : z4;
    As[0][lk + 0][lm] = va.x; As[0][lk + 1][lm] = va.y; As[0][lk + 2][lm] = va.z; As[0][lk + 3][lm] = va.w;
    Bs[0][lk + 0][lm] = vb.x; Bs[0][lk + 1][lm] = vb.y; Bs[0][lk + 2][lm] = vb.z; Bs[0][lk + 3][lm] = vb.w;
    __syncthreads();

    ull acc[8][4];
#pragma unroll
    for (int i = 0; i < 8; i++)
#pragma unroll
        for (int p = 0; p < 4; p++) acc[i][p] = 0ULL;

    int KT = K >> 3;
    for (int kt = 0; kt < KT; kt++) {
        int bf = kt & 1;
        float4 nva, nvb;
        if (kt + 1 < KT) {
            nva = av ? *(const float4*)(Ap + (kt + 1) * 8) : z4;
            nvb = bv ? *(const float4*)(Bp + (kt + 1) * 8) : z4;
        }
#pragma unroll
        for (int kk = 0; kk < 8; kk++) {
            float a[8], b[8];
            *(float4*)(a)     = *(const float4*)&As[bf][kk][ty << 2];
            *(float4*)(a + 4) = *(const float4*)&As[bf][kk][64 + (ty << 2)];
            *(float4*)(b)     = *(const float4*)&Bs[bf][kk][tx << 2];
            *(float4*)(b + 4) = *(const float4*)&Bs[bf][kk][64 + (tx << 2)];
            ull bp[4];
            bp[0] = pack2(b[0], b[1]); bp[1] = pack2(b[2], b[3]);
            bp[2] = pack2(b[4], b[5]); bp[3] = pack2(b[6], b[7]);
#pragma unroll
            for (int i = 0; i < 8; i++) {
                ull ad = pack2(a[i], a[i]);
                ffma2(acc[i][0], ad, bp[0]);
                ffma2(acc[i][1], ad, bp[1]);
                ffma2(acc[i][2], ad, bp[2]);
                ffma2(acc[i][3], ad, bp[3]);
            }
        }
        if (kt + 1 < KT) {
            int nb = bf ^ 1;
            As[nb][lk + 0][lm] = nva.x; As[nb][lk + 1][lm] = nva.y; As[nb][lk + 2][lm] = nva.z; As[nb][lk + 3][lm] = nva.w;
            Bs[nb][lk + 0][lm] = nvb.x; Bs[nb][lk + 1][lm] = nvb.y; Bs[nb][lk + 2][lm] = nvb.z; Bs[nb][lk + 3][lm] = nvb.w;
            __syncthreads();
        }
    }

#pragma unroll
    for (int i = 0; i < 8; i++) {
        int gm = row0 + ((i < 4) ? (ty << 2) + i : 64 + (ty << 2) + i - 4);
        bool rv = gm < M;
        float s = 0.f;
#pragma unroll
        for (int p = 0; p < 4; p++) {
            float v0, v1;
            unpack2(acc[i][p], v0, v1);
            int j0i = 2 * p;
            int gn0 = col0 + ((j0i < 4) ? (tx << 2) + j0i : 64 + (tx << 2) + j0i - 4);
            int gn1 = gn0 + 1;
            if (gn0 < N) {
                float v = v0 + (bias ? __ldg(&bias[gn0]) : 0.f);
                if (rv) C[(long)gm * ldc + gn0] = v;
                if (rowsum) s += fexp(v);
            }
            if (gn1 < N) {
                float v = v1 + (bias ? __ldg(&bias[gn1]) : 0.f);
                if (rv) C[(long)gm * ldc + gn1] = v;
                if (rowsum) s += fexp(v);
            }
        }
        if (rowsum) {
#pragma unroll
            for (int o = 8; o; o >>= 1) s += __shfl_xor_sync(0xffffffffu, s, o);
            if (tx == 0 && rv) atomicAdd(rowsum + gm, s);
        }
    }
}

// ---------------- generic batched TN SGEMM (64x64x16, FFMA2 core) ----------------
__global__ void __launch_bounds__(256) k_sgemm(
    const float* __restrict__ A, int lda, long sA,
    const float* __restrict__ Bw, int ldb, long sB,
    const float* __restrict__ bias,
    float* __restrict__ C, int ldc, long sC,
    int M, int N, int K)
{
    A  += (long)blockIdx.z * sA;
    Bw += (long)blockIdx.z * sB;
    C  += (long)blockIdx.z * sC;
    __shared__ float As[16][68];
    __shared__ float Bs[16][68];
    int tid = threadIdx.x;
    int tx = tid & 15, ty = tid >> 4;
    int row0 = blockIdx.y * 64, col0 = blockIdx.x * 64;
    int lm = tid >> 2, lk = (tid & 3) << 2;
    ull acc[4][2];
#pragma unroll
    for (int i = 0; i < 4; i++) { acc[i][0] = 0ULL; acc[i][1] = 0ULL; }

    for (int k0 = 0; k0 < K; k0 += 16) {
        float4 va = make_float4(0.f, 0.f, 0.f, 0.f);
        float4 vb = make_float4(0.f, 0.f, 0.f, 0.f);
        if (row0 + lm < M) va = *(const float4*)(A + (long)(row0 + lm) * lda + k0 + lk);
        if (col0 + lm < N) vb = *(const float4*)(Bw + (long)(col0 + lm) * ldb + k0 + lk);
        __syncthreads();
        As[lk][lm] = va.x; As[lk+1][lm] = va.y; As[lk+2][lm] = va.z; As[lk+3][lm] = va.w;
        Bs[lk][lm] = vb.x; Bs[lk+1][lm] = vb.y; Bs[lk+2][lm] = vb.z; Bs[lk+3][lm] = vb.w;
        __syncthreads();
#pragma unroll
        for (int kk = 0; kk < 16; kk++) {
            float4 a = *(const float4*)&As[kk][ty << 2];
            float4 b = *(const float4*)&Bs[kk][tx << 2];
            ull b01 = pack2(b.x, b.y), b23 = pack2(b.z, b.w);
            ull ad;
            ad = pack2(a.x, a.x); ffma2(acc[0][0], ad, b01); ffma2(acc[0][1], ad, b23);
            ad = pack2(a.y, a.y); ffma2(acc[1][0], ad, b01); ffma2(acc[1][1], ad, b23);
            ad = pack2(a.z, a.z); ffma2(acc[2][0], ad, b01); ffma2(acc[2][1], ad, b23);
            ad = pack2(a.w, a.w); ffma2(acc[3][0], ad, b01); ffma2(acc[3][1], ad, b23);
        }
    }
#pragma unroll
    for (int i = 0; i < 4; i++) {
        int gm = row0 + (ty << 2) + i;
        if (gm >= M) continue;
        float v[4];
        unpack2(acc[i][0], v[0], v[1]);
        unpack2(acc[i][1], v[2], v[3]);
#pragma unroll
        for (int j = 0; j < 4; j++) {
            int gn = col0 + (tx << 2) + j;
            if (gn >= N) continue;
            float w = v[j];
            if (bias) w += __ldg(&bias[gn]);
            C[(long)gm * ldc + gn] = w;
        }
    }
}

// ---------------- persistent bi-GRU encoder v2 ----------------
// 100 blocks (50/dir), 384 threads. Per block: 24 W-rows (3 gates x 8 j) x 400 K x 16 batch.
// Thread = (qg 0..5, rg 0..3, kp 0..15). W slice (4 rows x 25 k) cached in REGISTERS
// across all 256 timesteps; per step each thread loads only 100 h floats for 400 MACs.
__global__ void __launch_bounds__(384, 1) k_enc(
    const float* __restrict__ Whh_f, const float* __restrict__ Whh_b,
    const float* __restrict__ bhh_f, const float* __restrict__ bhh_b)
{
    __shared__ float hs[16 * 404];     // h staged [r][k], pad 404 (conflict-free)
    __shared__ float ghs[24 * 16];     // gh partials [q][r]
    __shared__ float bsh[24];

    int dir = (int)(blockIdx.x / 50);
    int jb  = (int)(blockIdx.x % 50);
    int j0  = jb * 8;
    const float* Whh = dir ? Whh_b : Whh_f;
    const float* bhh = dir ? bhh_b : bhh_f;
    const float* GI  = d_S + (dir ? OGI1 : OGI0);
    float* OUT = d_S + (dir ? OHB : OHF);
    int tid = threadIdx.x;

    int kp = tid & 15;          // k-partition (25 k each)
    int rg = (tid >> 4) & 3;    // r-group (4 rows)
    int qg = tid >> 6;          // q-group (4 W rows)
    int kbase = kp * 25;

    if (tid < 24) { int gate = tid >> 3, jl = tid & 7; bsh[tid] = bhh[gate * 400 + j0 + jl]; }

    // cache W slice in registers: rows q = qg*4+i, cols kbase..kbase+24
    float Wreg[4][25];
#pragma unroll
    for (int i = 0; i < 4; i++) {
        int q = qg * 4 + i;
        int gate = q >> 3, jl = q & 7;
        const float* wr = Whh + (long)(gate * 400 + j0 + jl) * 400 + kbase;
#pragma unroll
        for (int kk = 0; kk < 25; kk++) Wreg[i][kk] = wr[kk];
    }
    __syncthreads();

    for (int t = 0; t < TENC; ++t) {
        int p = t & 1;
        const float4* Hin4 = (const float4*)d_Hbuf[dir][p];
        float* Hout = d_Hbuf[dir][p ^ 1];

        // stage h into smem (L2 loads: bypass possibly-stale L1)
        for (int i4 = tid; i4 < 1600; i4 += 384) {
            float4 v = __ldcg(Hin4 + i4);
            int row = i4 / 100, c4 = (i4 % 100) << 2;
            *(float4*)&hs[row * 404 + c4] = v;
        }
        __syncthreads();

        // partial 4q x 4r tile over this thread's 25-k slice
        float acc[4][4];
#pragma unroll
        for (int i = 0; i < 4; i++)
#pragma unroll
            for (int j = 0; j < 4; j++) acc[i][j] = 0.f;

        const float* h0 = hs + (rg * 4 + 0) * 404 + kbase;
        const float* h1 = hs + (rg * 4 + 1) * 404 + kbase;
        const float* h2 = hs + (rg * 4 + 2) * 404 + kbase;
        const float* h3 = hs + (rg * 4 + 3) * 404 + kbase;
#pragma unroll
        for (int kk = 0; kk < 25; kk++) {
            float hv0 = h0[kk], hv1 = h1[kk], hv2 = h2[kk], hv3 = h3[kk];
#pragma unroll
            for (int i = 0; i < 4; i++) {
                float w = Wreg[i][kk];
                acc[i][0] += w * hv0;
                acc[i][1] += w * hv1;
                acc[i][2] += w * hv2;
                acc[i][3] += w * hv3;
            }
        }

        // butterfly-reduce over the 16 k-partitions (lanes of each 16-group)
#pragma unroll
        for (int i = 0; i < 4; i++)
#pragma unroll
            for (int j = 0; j < 4; j++) {
                float v = acc[i][j];
                v += __shfl_xor_sync(0xffffffffu, v, 1);
                v += __shfl_xor_sync(0xffffffffu, v, 2);
                v += __shfl_xor_sync(0xffffffffu, v, 4);
                v += __shfl_xor_sync(0xffffffffu, v, 8);
                acc[i][j] = v;
            }
        if (kp == 0) {
#pragma unroll
            for (int i = 0; i < 4; i++) {
                float bb = bsh[qg * 4 + i];
#pragma unroll
                for (int j = 0; j < 4; j++)
                    ghs[(qg * 4 + i) * 16 + (rg * 4 + j)] = acc[i][j] + bb;
            }
        }
        __syncthreads();

        if (tid < 128) {
            int rr = tid & 15, jj = tid >> 4;   // jj 0..7
            int time = dir ? (TENC - 1 - t) : t;
            long gib = ((long)time * Bb + rr) * H3 + j0 + jj;
            float ir = GI[gib], iz = GI[gib + 400], ig = GI[gib + 800];
            float hr_ = ghs[jj * 16 + rr];
            float hz_ = ghs[(8 + jj) * 16 + rr];
            float hg_ = ghs[(16 + jj) * 16 + rr];
            float hp  = hs[rr * 404 + j0 + jj];
            float rg_ = fsig(ir + hr_);
            float zg = fsig(iz + hz_);
            float gg = tanhf(ig + rg_ * hg_);
            float hn = (1.f - zg) * gg + zg * hp;
            Hout[rr * 400 + j0 + jj] = hn;
            OUT[((long)time * Bb + rr) * Hh + j0 + jj] = hn;
        }
        __syncthreads();                 // all h-stores of this block done
        if (tid == 0) {
            __threadfence();             // release
            unsigned a = atomicAdd(&g_barcnt[dir], 1u);
            if (a == 50u * (unsigned)(t + 1) - 1u) {
                atomicAdd(&g_bargen[dir], 1u);
            } else {
                while (__ldcg((const unsigned*)&g_bargen[dir]) < (unsigned)(t + 1)) { __nanosleep(32); }
            }
            __threadfence();             // acquire
        }
        __syncthreads();
    }
}

// ---------------- enc_out (B,T,H) and its transpose (B,H,T) ----------------
__global__ void k_encout() {
    long idx = (long)blockIdx.x * blockDim.x + threadIdx.x;
    if (idx >= (long)Bb * TENC * Hh) return;
    int b = (int)(idx / (TENC * Hh));
    int rem = (int)(idx % (TENC * Hh));
    int t = rem / Hh, h = rem % Hh;
    long src = ((long)t * Bb + b) * Hh + h;
    float v = d_S[OHF + src] + d_S[OHB + src];
    d_S[OEO + idx] = v;
    d_S[OEOT + (long)b * (Hh * TENC) + (long)h * TENC + t] = v;
}

// ---------------- decoder init: h = enc_hidden[b], din = slot_emb[s] ----------------
__global__ void k_dec_init(const float* __restrict__ slot) {
    int idx = blockIdx.x * blockDim.x + threadIdx.x;
    if (idx >= SB * Hh) return;
    int n = idx / Hh, h = idx % Hh;
    int s = n >> 4, b = n & 15;
    d_S[OH + idx]   = d_S[OHF + ((long)(TENC - 1) * Bb + b) * Hh + h]
                    + d_S[OHB + ((long)b) * Hh + h];
    d_S[ODIN + idx] = slot[s * Hh + h];
}

// ---------------- decoder GRU gates (in-place update of h); also zero rowsum ----------------
__global__ void k_dec_gates() {
    int idx = blockIdx.x * blockDim.x + threadIdx.x;
    if (idx < SB) d_S[ORSUM + idx] = 0.f;
    if (idx >= SB * Hh) return;
    int n = idx / Hh, j = idx % Hh;
    long gb = (long)n * H3 + j;
    float ir = d_S[OGI + gb], iz = d_S[OGI + gb + 400], ig = d_S[OGI + gb + 800];
    float hr = d_S[OGH + gb], hz = d_S[OGH + gb + 400], hg = d_S[OGH + gb + 800];
    float hp = d_S[OH + idx];
    float r = fsig(ir + hr);
    float z = fsig(iz + hz);
    float g = tanhf(ig + r * hg);
    d_S[OH + idx] = (1.f - z) * g + z * hp;
}

// ---------------- attention softmax over T=256 ----------------
__global__ void k_softmax_att() {
    int n = blockIdx.x, tid = threadIdx.x;
    __shared__ float red[256];
    float x = d_S[OPROB + (long)n * TENC + tid];
    red[tid] = x; __syncthreads();
    for (int o = 128; o; o >>= 1) { if (tid < o) red[tid] = fmaxf(red[tid], red[tid + o]); __syncthreads(); }
    float m = red[0]; __syncthreads();
    float e = fexp(x - m);
    red[tid] = e; __syncthreads();
    for (int o = 128; o; o >>= 1) { if (tid < o) red[tid] += red[tid + o]; __syncthreads(); }
    d_S[OPROB + (long)n * TENC + tid] = e / red[0];
}

// ---------------- sw (p_gen ratio) and (t==0) gate outputs ----------------
__global__ void k_sw_gate(const float* __restrict__ Wr, const float* __restrict__ br,
                          const float* __restrict__ Wg, const float* __restrict__ bg,
                          float* __restrict__ out, int t) {
    int warp = (blockIdx.x * blockDim.x + threadIdx.x) >> 5;
    int lane = threadIdx.x & 31;
    if (warp >= SB) return;
    int n = warp;
    float s = 0.f;
    for (int j = lane; j < H3; j += 32) {
        float v = (j < 400) ? d_S[OH + (long)n * Hh + j]
                : (j < 800) ? d_S[OCTX + (long)n * Hh + j - 400]
                            : d_S[ODIN + (long)n * Hh + j - 800];
        s += v * Wr[j];
    }
    for (int o = 16; o; o >>= 1) s += __shfl_xor_sync(0xffffffffu, s, o);
    if (lane == 0) d_S[OSW + n] = fsig(s + br[0]);
    if (t == 0) {
        for (int g = 0; g < Gg; g++) {
            float a = 0.f;
            for (int j = lane; j < Hh; j += 32) a += d_S[OCTX + (long)n * Hh + j] * Wg[g * Hh + j];
            for (int o = 16; o; o >>= 1) a += __shfl_xor_sync(0xffffffffu, a, o);
            if (lane == 0) out[PTR_OUT + (long)n * Gg + g] = a + bg[g];
        }
    }
}

// ---------------- write sw * p_vocab = sw * exp(l) / rowsum ----------------
__global__ void k_final(float* __restrict__ out, int t) {
    long idx = (long)blockIdx.x * blockDim.x + threadIdx.x;   // float4 index
    if (idx >= (long)SB * (Vv / 4)) return;
    int n = (int)(idx / (Vv / 4));
    int c = (int)(idx % (Vv / 4)) * 4;
    float4 l = *(const float4*)(d_S + OLOG + (long)n * Vv + c);
    float sc = d_S[OSW + n] / d_S[ORSUM + n];
    float4 o;
    o.x = fexp(l.x) * sc;
    o.y = fexp(l.y) * sc;
    o.z = fexp(l.z) * sc;
    o.w = fexp(l.w) * sc;
    *(float4*)(out + ((long)n * TDEC + t) * Vv + c) = o;
}

// ---------------- scatter-add pointer distribution ----------------
__global__ void k_scatter(float* __restrict__ out, const int* __restrict__ story, int t) {
    int idx = blockIdx.x * blockDim.x + threadIdx.x;
    if (idx >= SB * TENC) return;
    int n = idx >> 8, tt = idx & 255;
    int b = n & 15;
    int tok = story[b * TENC + tt];
    float v = (1.f - d_S[OSW + n]) * d_S[OPROB + (long)n * TENC + tt];
    atomicAdd(out + ((long)n * TDEC + t) * Vv + tok, v);
}

// ---------------- next decoder input: emb[tf_tokens[t]] ----------------
__global__ void k_next_din(const int* __restrict__ tb, const float* __restrict__ emb, int t) {
    int idx = blockIdx.x * blockDim.x + threadIdx.x;
    if (idx >= SB * Hh) return;
    int n = idx / Hh, h = idx % Hh;
    int s = n >> 4, b = n & 15;
    int tok = tb[(b * Ss + s) * TDEC + t];
    d_S[ODIN + idx] = emb[(long)tok * Hh + h];
}

// ---------------- host ----------------
extern "C" void kernel_launch(void* const* d_in, const int* in_sizes, int n_in,
                              void* d_out, int out_size) {
    const int*   story = (const int*)d_in[0];
    const int*   tb    = (const int*)d_in[1];
    const float* emb   = (const float*)d_in[2];
    const float* eWif  = (const float*)d_in[3];
    const float* eWhf  = (const float*)d_in[4];
    const float* ebif  = (const float*)d_in[5];
    const float* ebhf  = (const float*)d_in[6];
    const float* eWib  = (const float*)d_in[7];
    const float* eWhb  = (const float*)d_in[8];
    const float* ebib  = (const float*)d_in[9];
    const float* ebhb  = (const float*)d_in[10];
    const float* dWi   = (const float*)d_in[11];
    const float* dWh   = (const float*)d_in[12];
    const float* dbi   = (const float*)d_in[13];
    const float* dbh   = (const float*)d_in[14];
    const float* Wr    = (const float*)d_in[15];
    const float* br    = (const float*)d_in[16];
    const float* Wg    = (const float*)d_in[17];
    const float* bg    = (const float*)d_in[18];
    const float* slot  = (const float*)d_in[19];
    float* out = (float*)d_out;

    float* S = nullptr;
    cudaGetSymbolAddress((void**)&S, d_S);
    float* pX    = S + OX;
    float* pGI0  = S + OGI0;
    float* pGI1  = S + OGI1;
    float* pEO   = S + OEO;
    float* pEOT  = S + OEOT;
    float* pH    = S + OH;
    float* pDIN  = S + ODIN;
    float* pGI   = S + OGI;
    float* pGH   = S + OGH;
    float* pPROB = S + OPROB;
    float* pCTX  = S + OCTX;
    float* pRS   = S + ORSUM;
    float* pLOG  = S + OLOG;

    k_init<<<32, 256>>>();
    k_embed<<<(TENC * Bb * Hh + 255) / 256, 256>>>(story, emb);

    // GI (input gates) for both encoder directions: (4096 x 1200 x 400)
    k_sgemm<<<dim3(19, 64, 1), 256>>>(pX, Hh, 0, eWif, Hh, 0, ebif, pGI0, H3, 0, TENC * Bb, H3, Hh);
    k_sgemm<<<dim3(19, 64, 1), 256>>>(pX, Hh, 0, eWib, Hh, 0, ebib, pGI1, H3, 0, TENC * Bb, H3, Hh);

    // persistent bidirectional GRU (v2: W in registers)
    k_enc<<<100, 384>>>(eWhf, eWhb, ebhf, ebhb);

    k_encout<<<(Bb * TENC * Hh + 255) / 256, 256>>>();
    k_dec_init<<<(SB * Hh + 255) / 256, 256>>>(slot);

    for (int t = 0; t < TDEC; t++) {
        // GRU: gi = din@Wih^T+bih ; gh = h@Whh^T+bhh ; gates (+ zero rowsum)
        k_sgemm<<<dim3(19, 8, 1), 256>>>(pDIN, Hh, 0, dWi, Hh, 0, dbi, pGI, H3, 0, SB, H3, Hh);
        k_sgemm<<<dim3(19, 8, 1), 256>>>(pH,   Hh, 0, dWh, Hh, 0, dbh, pGH, H3, 0, SB, H3, Hh);
        k_dec_gates<<<(SB * Hh + 255) / 256, 256>>>();

        // attention: scores (batched over b), softmax, context (batched over b)
        k_sgemm<<<dim3(4, 1, Bb), 256>>>(pH, Bb * Hh, Hh, pEO, Hh, (long)TENC * Hh,
                                         nullptr, pPROB, Bb * TENC, TENC, Ss, TENC, Hh);
        k_softmax_att<<<SB, 256>>>();
        k_sgemm<<<dim3(7, 1, Bb), 256>>>(pPROB, Bb * TENC, TENC, pEOT, TENC, (long)Hh * TENC,
                                         nullptr, pCTX, Bb * Hh, Hh, Ss, Hh, TENC);

        k_sw_gate<<<60, 256>>>(Wr, br, Wg, bg, out, t);

        // vocab logits + fused row-sum-of-exp epilogue
        k_gemm128<<<dim3(141, 4), 256>>>(pH, Hh, emb, Hh, nullptr, pLOG, Vv, pRS, SB, Vv, Hh);
        k_final<<<(SB * (Vv / 4) + 255) / 256, 256>>>(out, t);
        k_scatter<<<SB, 256>>>(out, story, t);

        k_next_din<<<(SB * Hh + 255) / 256, 256>>>(tb, emb, t);
    }
}

// round 8
// speedup vs baseline: 1.4156x; 1.0533x over previous
#include <cuda_runtime.h>
#include <cuda_bf16.h>
#include <math.h>

#define Vv 18000
#define Hh 400
#define Bb 16
#define TENC 256
#define Ss 30
#define TDEC 8
#define Gg 3
#define SB 480
#define H3 1200
#define PTR_OUT 69120000L

typedef unsigned long long ull;
typedef unsigned int u32;

// ---------------- scratch ----------------
#define OX    0L
#define OGI0  1638400L
#define OGI1  6553600L
#define OHF   11468800L
#define OHB   13107200L
#define OEO   14745600L
#define OEOT  16384000L
#define OH    18022400L
#define ODIN  18214400L
#define OGI   18406400L
#define OGH   18982400L
#define OPROB 19558400L
#define OCTX  19681280L
#define OSW   19873280L
#define ORSUM 19873760L
#define OLOG  19874720L
#define STOT  28514720L

__device__ float d_S[STOT];
__device__ float d_Hbuf[2][2][Bb * Hh];
__device__ unsigned g_barcnt[2], g_bargen[2];
// bf16 split operands for tensor-core logits GEMM
__device__ __nv_bfloat16 d_ehi[(long)Vv * Hh];
__device__ __nv_bfloat16 d_elo[(long)Vv * Hh];
__device__ __nv_bfloat16 d_hhi[SB * Hh];
__device__ __nv_bfloat16 d_hlo[SB * Hh];

// ---------------- fast exp (FMA-only, rel err ~1e-7) ----------------
__device__ __forceinline__ float fexp(float x) {
    x = fminf(fmaxf(x, -80.0f), 80.0f);
    float y = x * 1.4426950408889634f;
    int   i = __float2int_rn(y);
    float f = y - (float)i;
    float u = f * 0.6931471805599453f;
    float p = 1.0f + u * (1.0f + u * (0.5f + u * (0.16666667f +
              u * (0.041666668f + u * (0.008333334f + u * 0.0013888889f)))));
    return __int_as_float(__float_as_int(p) + (i << 23));
}
__device__ __forceinline__ float fsig(float x) { return 1.0f / (1.0f + fexp(-x)); }

// ---------------- bf16 split helper ----------------
__device__ __forceinline__ void bsplit(float v, __nv_bfloat16& hi, __nv_bfloat16& lo) {
    hi = __float2bfloat16(v);
    lo = __float2bfloat16(v - __bfloat162float(hi));
}

// ---------------- mma.sync bf16 m16n8k16, fp32 accum ----------------
__device__ __forceinline__ void mma_bf16(float* c, const u32* a, const u32* b) {
    asm volatile(
        "mma.sync.aligned.m16n8k16.row.col.f32.bf16.bf16.f32 "
        "{%0,%1,%2,%3}, {%4,%5,%6,%7}, {%8,%9}, {%0,%1,%2,%3};"
        : "+f"(c[0]), "+f"(c[1]), "+f"(c[2]), "+f"(c[3])
        : "r"(a[0]), "r"(a[1]), "r"(a[2]), "r"(a[3]), "r"(b[0]), "r"(b[1]));
}

// ---------------- init ----------------
__global__ void k_init() {
    int tid = blockIdx.x * blockDim.x + threadIdx.x;
    if (tid == 0) {
        g_barcnt[0] = 0u; g_barcnt[1] = 0u;
        g_bargen[0] = 0u; g_bargen[1] = 0u;
    }
    for (int i = tid; i < 2 * 2 * Bb * Hh; i += gridDim.x * blockDim.x)
        ((float*)d_Hbuf)[i] = 0.0f;
}

// ---------------- embed story + one-time emb bf16 split ----------------
__global__ void k_embed(const int* __restrict__ story, const float* __restrict__ emb) {
    long idx = (long)blockIdx.x * blockDim.x + threadIdx.x;
    if (idx >= (long)TENC * Bb * Hh) return;
    int h = (int)(idx % Hh);
    int tb = (int)(idx / Hh);
    int b = tb & 15, t = tb >> 4;
    d_S[OX + idx] = emb[(long)story[b * TENC + t] * Hh + h];
}

__global__ void k_embconv(const float* __restrict__ emb) {
    long idx = (long)blockIdx.x * blockDim.x + threadIdx.x;
    if (idx >= (long)Vv * Hh) return;
    bsplit(emb[idx], d_ehi[idx], d_elo[idx]);
}

// ---------------- generic batched TN SGEMM (64x64x16) ----------------
__global__ void __launch_bounds__(256) k_sgemm(
    const float* __restrict__ A, int lda, long sA,
    const float* __restrict__ Bw, int ldb, long sB,
    const float* __restrict__ bias,
    float* __restrict__ C, int ldc, long sC,
    int M, int N, int K)
{
    A  += (long)blockIdx.z * sA;
    Bw += (long)blockIdx.z * sB;
    C  += (long)blockIdx.z * sC;
    __shared__ float As[16][68];
    __shared__ float Bs[16][68];
    int tid = threadIdx.x;
    int tx = tid & 15, ty = tid >> 4;
    int row0 = blockIdx.y * 64, col0 = blockIdx.x * 64;
    int lm = tid >> 2, lk = (tid & 3) << 2;
    float acc[4][4] = {{0.f}};

    for (int k0 = 0; k0 < K; k0 += 16) {
        float4 va = make_float4(0.f, 0.f, 0.f, 0.f);
        float4 vb = make_float4(0.f, 0.f, 0.f, 0.f);
        if (row0 + lm < M) va = *(const float4*)(A + (long)(row0 + lm) * lda + k0 + lk);
        if (col0 + lm < N) vb = *(const float4*)(Bw + (long)(col0 + lm) * ldb + k0 + lk);
        __syncthreads();
        As[lk][lm] = va.x; As[lk+1][lm] = va.y; As[lk+2][lm] = va.z; As[lk+3][lm] = va.w;
        Bs[lk][lm] = vb.x; Bs[lk+1][lm] = vb.y; Bs[lk+2][lm] = vb.z; Bs[lk+3][lm] = vb.w;
        __syncthreads();
#pragma unroll
        for (int kk = 0; kk < 16; kk++) {
            float4 a = *(const float4*)&As[kk][ty << 2];
            float4 b = *(const float4*)&Bs[kk][tx << 2];
            acc[0][0] += a.x*b.x; acc[0][1] += a.x*b.y; acc[0][2] += a.x*b.z; acc[0][3] += a.x*b.w;
            acc[1][0] += a.y*b.x; acc[1][1] += a.y*b.y; acc[1][2] += a.y*b.z; acc[1][3] += a.y*b.w;
            acc[2][0] += a.z*b.x; acc[2][1] += a.z*b.y; acc[2][2] += a.z*b.z; acc[2][3] += a.z*b.w;
            acc[3][0] += a.w*b.x; acc[3][1] += a.w*b.y; acc[3][2] += a.w*b.z; acc[3][3] += a.w*b.w;
        }
    }
#pragma unroll
    for (int i = 0; i < 4; i++) {
        int gm = row0 + (ty << 2) + i;
        if (gm >= M) continue;
#pragma unroll
        for (int j = 0; j < 4; j++) {
            int gn = col0 + (tx << 2) + j;
            if (gn >= N) continue;
            float v = acc[i][j];
            if (bias) v += __ldg(&bias[gn]);
            C[(long)gm * ldc + gn] = v;
        }
    }
}

// ---------------- tensor-core logits: C[480,18000] = h @ emb^T (split bf16) ----------------
// block 256 thr = 8 warps (2 M x 4 N). Block tile 32x256, warp tile 16x64.
// Fused epilogue: rowsum[m] += sum_n exp(C[m][n]).
__global__ void __launch_bounds__(256) k_mmalog(float* __restrict__ C,
                                               float* __restrict__ rowsum) {
    __shared__ __nv_bfloat16 As[2][32][18];
    __shared__ __nv_bfloat16 Bs[2][256][18];
    int tid = threadIdx.x;
    int warp = tid >> 5, lane = tid & 31;
    int wm = warp >> 2, wn = warp & 3;
    int g = lane >> 2, tig = lane & 3;
    int m0 = blockIdx.y * 32, n0 = blockIdx.x * 256;

    float c[8][4];
#pragma unroll
    for (int s = 0; s < 8; s++)
#pragma unroll
        for (int q = 0; q < 4; q++) c[s][q] = 0.f;

    for (int kc = 0; kc < Hh; kc += 16) {
        __syncthreads();
        // A: 32 rows x 8 pairs (one pair-slot per thread)
        {
            int row = tid >> 3, pr = tid & 7;
            long gi = (long)(m0 + row) * Hh + kc + pr * 2;
            *(u32*)&As[0][row][pr * 2] = *(const u32*)(d_hhi + gi);
            *(u32*)&As[1][row][pr * 2] = *(const u32*)(d_hlo + gi);
        }
        // B: 256 rows x 8 pairs
#pragma unroll
        for (int it = 0; it < 8; it++) {
            int idx = it * 256 + tid;
            int row = idx >> 3, pr = idx & 7;
            int n = n0 + row;
            u32 vh = 0u, vl = 0u;
            if (n < Vv) {
                long gi = (long)n * Hh + kc + pr * 2;
                vh = *(const u32*)(d_ehi + gi);
                vl = *(const u32*)(d_elo + gi);
            }
            *(u32*)&Bs[0][row][pr * 2] = vh;
            *(u32*)&Bs[1][row][pr * 2] = vl;
        }
        __syncthreads();

        u32 ah[4], al[4];
        int ar = wm * 16 + g;
        ah[0] = *(u32*)&As[0][ar][tig * 2];
        ah[1] = *(u32*)&As[0][ar + 8][tig * 2];
        ah[2] = *(u32*)&As[0][ar][tig * 2 + 8];
        ah[3] = *(u32*)&As[0][ar + 8][tig * 2 + 8];
        al[0] = *(u32*)&As[1][ar][tig * 2];
        al[1] = *(u32*)&As[1][ar + 8][tig * 2];
        al[2] = *(u32*)&As[1][ar][tig * 2 + 8];
        al[3] = *(u32*)&As[1][ar + 8][tig * 2 + 8];

#pragma unroll
        for (int sub = 0; sub < 8; sub++) {
            int bn = wn * 64 + sub * 8 + g;
            u32 bh[2], bl[2];
            bh[0] = *(u32*)&Bs[0][bn][tig * 2];
            bh[1] = *(u32*)&Bs[0][bn][tig * 2 + 8];
            bl[0] = *(u32*)&Bs[1][bn][tig * 2];
            bl[1] = *(u32*)&Bs[1][bn][tig * 2 + 8];
            mma_bf16(c[sub], ah, bh);   // hi*hi
            mma_bf16(c[sub], ah, bl);   // hi*lo
            mma_bf16(c[sub], al, bh);   // lo*hi
        }
    }

    // epilogue: store logits + exp-rowsum
    int gmA = m0 + wm * 16 + g;
    int gmB = gmA + 8;
    float sA = 0.f, sB = 0.f;
#pragma unroll
    for (int sub = 0; sub < 8; sub++) {
        int gn = n0 + wn * 64 + sub * 8 + tig * 2;
        if (gn < Vv) {
            *(float2*)(C + (long)gmA * Vv + gn) = make_float2(c[sub][0], c[sub][1]);
            *(float2*)(C + (long)gmB * Vv + gn) = make_float2(c[sub][2], c[sub][3]);
            sA += fexp(c[sub][0]) + fexp(c[sub][1]);
            sB += fexp(c[sub][2]) + fexp(c[sub][3]);
        }
    }
    sA += __shfl_xor_sync(0xffffffffu, sA, 1);
    sA += __shfl_xor_sync(0xffffffffu, sA, 2);
    sB += __shfl_xor_sync(0xffffffffu, sB, 1);
    sB += __shfl_xor_sync(0xffffffffu, sB, 2);
    if (tig == 0) {
        atomicAdd(rowsum + gmA, sA);
        atomicAdd(rowsum + gmB, sB);
    }
}

// ---------------- persistent bi-GRU encoder (v2 + GI prefetch) ----------------
__global__ void __launch_bounds__(384, 1) k_enc(
    const float* __restrict__ Whh_f, const float* __restrict__ Whh_b,
    const float* __restrict__ bhh_f, const float* __restrict__ bhh_b)
{
    __shared__ float hs[16 * 404];
    __shared__ float ghs[24 * 16];
    __shared__ float bsh[24];

    int dir = (int)(blockIdx.x / 50);
    int jb  = (int)(blockIdx.x % 50);
    int j0  = jb * 8;
    const float* Whh = dir ? Whh_b : Whh_f;
    const float* bhh = dir ? bhh_b : bhh_f;
    const float* GI  = d_S + (dir ? OGI1 : OGI0);
    float* OUT = d_S + (dir ? OHB : OHF);
    int tid = threadIdx.x;

    int kp = tid & 15;
    int rgi = (tid >> 4) & 3;
    int qg = tid >> 6;
    int kbase = kp * 25;

    if (tid < 24) { int gate = tid >> 3, jl = tid & 7; bsh[tid] = bhh[gate * 400 + j0 + jl]; }

    float Wreg[4][25];
#pragma unroll
    for (int i = 0; i < 4; i++) {
        int q = qg * 4 + i;
        int gate = q >> 3, jl = q & 7;
        const float* wr = Whh + (long)(gate * 400 + j0 + jl) * 400 + kbase;
#pragma unroll
        for (int kk = 0; kk < 25; kk++) Wreg[i][kk] = wr[kk];
    }
    __syncthreads();

    for (int t = 0; t < TENC; ++t) {
        int p = t & 1;
        const float4* Hin4 = (const float4*)d_Hbuf[dir][p];
        float* Hout = d_Hbuf[dir][p ^ 1];

        // prefetch GI early — independent of h, overlaps L2 latency with compute
        float ir = 0.f, iz = 0.f, ig = 0.f;
        int time = dir ? (TENC - 1 - t) : t;
        if (tid < 128) {
            int rr = tid & 15, jj = tid >> 4;
            long gib = ((long)time * Bb + rr) * H3 + j0 + jj;
            ir = GI[gib]; iz = GI[gib + 400]; ig = GI[gib + 800];
        }

        // stage h into smem
        for (int i4 = tid; i4 < 1600; i4 += 384) {
            float4 v = __ldcg(Hin4 + i4);
            int row = i4 / 100, c4 = (i4 % 100) << 2;
            *(float4*)&hs[row * 404 + c4] = v;
        }
        __syncthreads();

        float acc[4][4];
#pragma unroll
        for (int i = 0; i < 4; i++)
#pragma unroll
            for (int j = 0; j < 4; j++) acc[i][j] = 0.f;

        const float* h0 = hs + (rgi * 4 + 0) * 404 + kbase;
        const float* h1 = hs + (rgi * 4 + 1) * 404 + kbase;
        const float* h2 = hs + (rgi * 4 + 2) * 404 + kbase;
        const float* h3 = hs + (rgi * 4 + 3) * 404 + kbase;
#pragma unroll
        for (int kk = 0; kk < 25; kk++) {
            float hv0 = h0[kk], hv1 = h1[kk], hv2 = h2[kk], hv3 = h3[kk];
#pragma unroll
            for (int i = 0; i < 4; i++) {
                float w = Wreg[i][kk];
                acc[i][0] += w * hv0;
                acc[i][1] += w * hv1;
                acc[i][2] += w * hv2;
                acc[i][3] += w * hv3;
            }
        }

#pragma unroll
        for (int i = 0; i < 4; i++)
#pragma unroll
            for (int j = 0; j < 4; j++) {
                float v = acc[i][j];
                v += __shfl_xor_sync(0xffffffffu, v, 1);
                v += __shfl_xor_sync(0xffffffffu, v, 2);
                v += __shfl_xor_sync(0xffffffffu, v, 4);
                v += __shfl_xor_sync(0xffffffffu, v, 8);
                acc[i][j] = v;
            }
        if (kp == 0) {
#pragma unroll
            for (int i = 0; i < 4; i++) {
                float bb = bsh[qg * 4 + i];
#pragma unroll
                for (int j = 0; j < 4; j++)
                    ghs[(qg * 4 + i) * 16 + (rgi * 4 + j)] = acc[i][j] + bb;
            }
        }
        __syncthreads();

        if (tid < 128) {
            int rr = tid & 15, jj = tid >> 4;
            float hr_ = ghs[jj * 16 + rr];
            float hz_ = ghs[(8 + jj) * 16 + rr];
            float hg_ = ghs[(16 + jj) * 16 + rr];
            float hp  = hs[rr * 404 + j0 + jj];
            float rg_ = fsig(ir + hr_);
            float zg = fsig(iz + hz_);
            float gg = tanhf(ig + rg_ * hg_);
            float hn = (1.f - zg) * gg + zg * hp;
            Hout[rr * 400 + j0 + jj] = hn;
            OUT[((long)time * Bb + rr) * Hh + j0 + jj] = hn;
        }
        __syncthreads();
        if (tid == 0) {
            __threadfence();
            unsigned a = atomicAdd(&g_barcnt[dir], 1u);
            if (a == 50u * (unsigned)(t + 1) - 1u) {
                atomicAdd(&g_bargen[dir], 1u);
            } else {
                while (__ldcg((const unsigned*)&g_bargen[dir]) < (unsigned)(t + 1)) { __nanosleep(32); }
            }
            __threadfence();
        }
        __syncthreads();
    }
}

// ---------------- enc_out (B,T,H) and its transpose (B,H,T) ----------------
__global__ void k_encout() {
    long idx = (long)blockIdx.x * blockDim.x + threadIdx.x;
    if (idx >= (long)Bb * TENC * Hh) return;
    int b = (int)(idx / (TENC * Hh));
    int rem = (int)(idx % (TENC * Hh));
    int t = rem / Hh, h = rem % Hh;
    long src = ((long)t * Bb + b) * Hh + h;
    float v = d_S[OHF + src] + d_S[OHB + src];
    d_S[OEO + idx] = v;
    d_S[OEOT + (long)b * (Hh * TENC) + (long)h * TENC + t] = v;
}

// ---------------- decoder init ----------------
__global__ void k_dec_init(const float* __restrict__ slot) {
    int idx = blockIdx.x * blockDim.x + threadIdx.x;
    if (idx >= SB * Hh) return;
    int n = idx / Hh, h = idx % Hh;
    int s = n >> 4, b = n & 15;
    d_S[OH + idx]   = d_S[OHF + ((long)(TENC - 1) * Bb + b) * Hh + h]
                    + d_S[OHB + ((long)b) * Hh + h];
    d_S[ODIN + idx] = slot[s * Hh + h];
}

// ---------------- decoder GRU gates; also zero rowsum + bf16 split of h ----------------
__global__ void k_dec_gates() {
    int idx = blockIdx.x * blockDim.x + threadIdx.x;
    if (idx < SB) d_S[ORSUM + idx] = 0.f;
    if (idx >= SB * Hh) return;
    int n = idx / Hh, j = idx % Hh;
    long gb = (long)n * H3 + j;
    float ir = d_S[OGI + gb], iz = d_S[OGI + gb + 400], ig = d_S[OGI + gb + 800];
    float hr = d_S[OGH + gb], hz = d_S[OGH + gb + 400], hg = d_S[OGH + gb + 800];
    float hp = d_S[OH + idx];
    float r = fsig(ir + hr);
    float z = fsig(iz + hz);
    float g = tanhf(ig + r * hg);
    float hn = (1.f - z) * g + z * hp;
    d_S[OH + idx] = hn;
    bsplit(hn, d_hhi[idx], d_hlo[idx]);
}

// ---------------- attention softmax over T=256 ----------------
__global__ void k_softmax_att() {
    int n = blockIdx.x, tid = threadIdx.x;
    __shared__ float red[256];
    float x = d_S[OPROB + (long)n * TENC + tid];
    red[tid] = x; __syncthreads();
    for (int o = 128; o; o >>= 1) { if (tid < o) red[tid] = fmaxf(red[tid], red[tid + o]); __syncthreads(); }
    float m = red[0]; __syncthreads();
    float e = fexp(x - m);
    red[tid] = e; __syncthreads();
    for (int o = 128; o; o >>= 1) { if (tid < o) red[tid] += red[tid + o]; __syncthreads(); }
    d_S[OPROB + (long)n * TENC + tid] = e / red[0];
}

// ---------------- sw (p_gen ratio) and (t==0) gate outputs ----------------
__global__ void k_sw_gate(const float* __restrict__ Wr, const float* __restrict__ br,
                          const float* __restrict__ Wg, const float* __restrict__ bg,
                          float* __restrict__ out, int t) {
    int warp = (blockIdx.x * blockDim.x + threadIdx.x) >> 5;
    int lane = threadIdx.x & 31;
    if (warp >= SB) return;
    int n = warp;
    float s = 0.f;
    for (int j = lane; j < H3; j += 32) {
        float v = (j < 400) ? d_S[OH + (long)n * Hh + j]
                : (j < 800) ? d_S[OCTX + (long)n * Hh + j - 400]
                            : d_S[ODIN + (long)n * Hh + j - 800];
        s += v * Wr[j];
    }
    for (int o = 16; o; o >>= 1) s += __shfl_xor_sync(0xffffffffu, s, o);
    if (lane == 0) d_S[OSW + n] = fsig(s + br[0]);
    if (t == 0) {
        for (int g = 0; g < Gg; g++) {
            float a = 0.f;
            for (int j = lane; j < Hh; j += 32) a += d_S[OCTX + (long)n * Hh + j] * Wg[g * Hh + j];
            for (int o = 16; o; o >>= 1) a += __shfl_xor_sync(0xffffffffu, a, o);
            if (lane == 0) out[PTR_OUT + (long)n * Gg + g] = a + bg[g];
        }
    }
}

// ---------------- write sw * p_vocab = sw * exp(l) / rowsum ----------------
__global__ void k_final(float* __restrict__ out, int t) {
    long idx = (long)blockIdx.x * blockDim.x + threadIdx.x;
    if (idx >= (long)SB * (Vv / 4)) return;
    int n = (int)(idx / (Vv / 4));
    int c = (int)(idx % (Vv / 4)) * 4;
    float4 l = *(const float4*)(d_S + OLOG + (long)n * Vv + c);
    float sc = d_S[OSW + n] / d_S[ORSUM + n];
    float4 o;
    o.x = fexp(l.x) * sc;
    o.y = fexp(l.y) * sc;
    o.z = fexp(l.z) * sc;
    o.w = fexp(l.w) * sc;
    *(float4*)(out + ((long)n * TDEC + t) * Vv + c) = o;
}

// ---------------- scatter-add pointer distribution ----------------
__global__ void k_scatter(float* __restrict__ out, const int* __restrict__ story, int t) {
    int idx = blockIdx.x * blockDim.x + threadIdx.x;
    if (idx >= SB * TENC) return;
    int n = idx >> 8, tt = idx & 255;
    int b = n & 15;
    int tok = story[b * TENC + tt];
    float v = (1.f - d_S[OSW + n]) * d_S[OPROB + (long)n * TENC + tt];
    atomicAdd(out + ((long)n * TDEC + t) * Vv + tok, v);
}

// ---------------- next decoder input ----------------
__global__ void k_next_din(const int* __restrict__ tb, const float* __restrict__ emb, int t) {
    int idx = blockIdx.x * blockDim.x + threadIdx.x;
    if (idx >= SB * Hh) return;
    int n = idx / Hh, h = idx % Hh;
    int s = n >> 4, b = n & 15;
    int tok = tb[(b * Ss + s) * TDEC + t];
    d_S[ODIN + idx] = emb[(long)tok * Hh + h];
}

// ---------------- host ----------------
extern "C" void kernel_launch(void* const* d_in, const int* in_sizes, int n_in,
                              void* d_out, int out_size) {
    const int*   story = (const int*)d_in[0];
    const int*   tb    = (const int*)d_in[1];
    const float* emb   = (const float*)d_in[2];
    const float* eWif  = (const float*)d_in[3];
    const float* eWhf  = (const float*)d_in[4];
    const float* ebif  = (const float*)d_in[5];
    const float* ebhf  = (const float*)d_in[6];
    const float* eWib  = (const float*)d_in[7];
    const float* eWhb  = (const float*)d_in[8];
    const float* ebib  = (const float*)d_in[9];
    const float* ebhb  = (const float*)d_in[10];
    const float* dWi   = (const float*)d_in[11];
    const float* dWh   = (const float*)d_in[12];
    const float* dbi   = (const float*)d_in[13];
    const float* dbh   = (const float*)d_in[14];
    const float* Wr    = (const float*)d_in[15];
    const float* br    = (const float*)d_in[16];
    const float* Wg    = (const float*)d_in[17];
    const float* bg    = (const float*)d_in[18];
    const float* slot  = (const float*)d_in[19];
    float* out = (float*)d_out;

    float* S = nullptr;
    cudaGetSymbolAddress((void**)&S, d_S);
    float* pX    = S + OX;
    float* pGI0  = S + OGI0;
    float* pGI1  = S + OGI1;
    float* pEO   = S + OEO;
    float* pEOT  = S + OEOT;
    float* pH    = S + OH;
    float* pDIN  = S + ODIN;
    float* pGI   = S + OGI;
    float* pGH   = S + OGH;
    float* pPROB = S + OPROB;
    float* pCTX  = S + OCTX;
    float* pRS   = S + ORSUM;
    float* pLOG  = S + OLOG;

    k_init<<<32, 256>>>();
    k_embed<<<(TENC * Bb * Hh + 255) / 256, 256>>>(story, emb);
    k_embconv<<<(int)(((long)Vv * Hh + 255) / 256), 256>>>(emb);

    // GI for both encoder directions: (4096 x 1200 x 400)
    k_sgemm<<<dim3(19, 64, 1), 256>>>(pX, Hh, 0, eWif, Hh, 0, ebif, pGI0, H3, 0, TENC * Bb, H3, Hh);
    k_sgemm<<<dim3(19, 64, 1), 256>>>(pX, Hh, 0, eWib, Hh, 0, ebib, pGI1, H3, 0, TENC * Bb, H3, Hh);

    // persistent bidirectional GRU
    k_enc<<<100, 384>>>(eWhf, eWhb, ebhf, ebhb);

    k_encout<<<(Bb * TENC * Hh + 255) / 256, 256>>>();
    k_dec_init<<<(SB * Hh + 255) / 256, 256>>>(slot);

    for (int t = 0; t < TDEC; t++) {
        k_sgemm<<<dim3(19, 8, 1), 256>>>(pDIN, Hh, 0, dWi, Hh, 0, dbi, pGI, H3, 0, SB, H3, Hh);
        k_sgemm<<<dim3(19, 8, 1), 256>>>(pH,   Hh, 0, dWh, Hh, 0, dbh, pGH, H3, 0, SB, H3, Hh);
        k_dec_gates<<<(SB * Hh + 255) / 256, 256>>>();

        k_sgemm<<<dim3(4, 1, Bb), 256>>>(pH, Bb * Hh, Hh, pEO, Hh, (long)TENC * Hh,
                                         nullptr, pPROB, Bb * TENC, TENC, Ss, TENC, Hh);
        k_softmax_att<<<SB, 256>>>();
        k_sgemm<<<dim3(7, 1, Bb), 256>>>(pPROB, Bb * TENC, TENC, pEOT, TENC, (long)Hh * TENC,
                                         nullptr, pCTX, Bb * Hh, Hh, Ss, Hh, TENC);

        k_sw_gate<<<60, 256>>>(Wr, br, Wg, bg, out, t);

        // tensor-core vocab logits + fused exp-rowsum
        k_mmalog<<<dim3(71, 15), 256>>>(pLOG, pRS);
        k_final<<<(SB * (Vv / 4) + 255) / 256, 256>>>(out, t);
        k_scatter<<<SB, 256>>>(out, story, t);

        k_next_din<<<(SB * Hh + 255) / 256, 256>>>(tb, emb, t);
    }
}

// round 9
// speedup vs baseline: 1.6481x; 1.1642x over previous
#include <cuda_runtime.h>
#include <cuda_bf16.h>
#include <math.h>

#define Vv 18000
#define Hh 400
#define Bb 16
#define TENC 256
#define Ss 30
#define TDEC 8
#define Gg 3
#define SB 480
#define H3 1200
#define PTR_OUT 69120000L

typedef unsigned long long ull;
typedef unsigned int u32;

// ---------------- scratch ----------------
#define OX    0L
#define OGI0  1638400L
#define OGI1  6553600L
#define OHF   11468800L
#define OHB   13107200L
#define OEO   14745600L
#define OEOT  16384000L
#define OH    18022400L
#define ODIN  18214400L
#define OGI   18406400L
#define OGH   18982400L
#define OPROB 19558400L
#define OCTX  19681280L
#define OSW   19873280L
#define ORSUM 19873760L
#define STOT  19874720L

__device__ float d_S[STOT];
__device__ float d_Hbuf[2][2][Bb * Hh];
__device__ unsigned g_barcnt[2], g_bargen[2];
// bf16 split operands for tensor-core GEMMs
__device__ __nv_bfloat16 d_ehi[(long)Vv * Hh];
__device__ __nv_bfloat16 d_elo[(long)Vv * Hh];
__device__ __nv_bfloat16 d_hhi[SB * Hh];
__device__ __nv_bfloat16 d_hlo[SB * Hh];
__device__ __nv_bfloat16 d_xhi[TENC * Bb * Hh];
__device__ __nv_bfloat16 d_xlo[TENC * Bb * Hh];
__device__ __nv_bfloat16 d_wfhi[H3 * Hh], d_wflo[H3 * Hh];
__device__ __nv_bfloat16 d_wbhi[H3 * Hh], d_wblo[H3 * Hh];

// ---------------- fast exp (FMA-only, rel err ~1e-7) ----------------
__device__ __forceinline__ float fexp(float x) {
    x = fminf(fmaxf(x, -80.0f), 80.0f);
    float y = x * 1.4426950408889634f;
    int   i = __float2int_rn(y);
    float f = y - (float)i;
    float u = f * 0.6931471805599453f;
    float p = 1.0f + u * (1.0f + u * (0.5f + u * (0.16666667f +
              u * (0.041666668f + u * (0.008333334f + u * 0.0013888889f)))));
    return __int_as_float(__float_as_int(p) + (i << 23));
}
__device__ __forceinline__ float fsig(float x) { return 1.0f / (1.0f + fexp(-x)); }

__device__ __forceinline__ void bsplit(float v, __nv_bfloat16& hi, __nv_bfloat16& lo) {
    hi = __float2bfloat16(v);
    lo = __float2bfloat16(v - __bfloat162float(hi));
}

// ---------------- mma.sync bf16 m16n8k16, fp32 accum ----------------
__device__ __forceinline__ void mma_bf16(float* c, const u32* a, const u32* b) {
    asm volatile(
        "mma.sync.aligned.m16n8k16.row.col.f32.bf16.bf16.f32 "
        "{%0,%1,%2,%3}, {%4,%5,%6,%7}, {%8,%9}, {%0,%1,%2,%3};"
        : "+f"(c[0]), "+f"(c[1]), "+f"(c[2]), "+f"(c[3])
        : "r"(a[0]), "r"(a[1]), "r"(a[2]), "r"(a[3]), "r"(b[0]), "r"(b[1]));
}

// ---------------- init ----------------
__global__ void k_init() {
    int tid = blockIdx.x * blockDim.x + threadIdx.x;
    if (tid == 0) {
        g_barcnt[0] = 0u; g_barcnt[1] = 0u;
        g_bargen[0] = 0u; g_bargen[1] = 0u;
    }
    for (int i = tid; i < 2 * 2 * Bb * Hh; i += gridDim.x * blockDim.x)
        ((float*)d_Hbuf)[i] = 0.0f;
}

// ---------------- one-time conversions ----------------
__global__ void k_embconv(const float* __restrict__ emb) {
    long idx = (long)blockIdx.x * blockDim.x + threadIdx.x;
    if (idx >= (long)Vv * Hh) return;
    bsplit(emb[idx], d_ehi[idx], d_elo[idx]);
}
__global__ void k_wsplit(const float* __restrict__ w, __nv_bfloat16* hi, __nv_bfloat16* lo, int n) {
    int idx = blockIdx.x * blockDim.x + threadIdx.x;
    if (idx >= n) return;
    bsplit(w[idx], hi[idx], lo[idx]);
}
// embed story directly into split form (gather from split emb)
__global__ void k_embed(const int* __restrict__ story) {
    long idx = (long)blockIdx.x * blockDim.x + threadIdx.x;
    if (idx >= (long)TENC * Bb * Hh) return;
    int h = (int)(idx % Hh);
    int tb = (int)(idx / Hh);
    int b = tb & 15, t = tb >> 4;
    long src = (long)story[b * TENC + t] * Hh + h;
    d_xhi[idx] = d_ehi[src];
    d_xlo[idx] = d_elo[src];
}

// ---------------- generic batched TN SGEMM (64x64x16) — small decoder shapes ----------------
__global__ void __launch_bounds__(256) k_sgemm(
    const float* __restrict__ A, int lda, long sA,
    const float* __restrict__ Bw, int ldb, long sB,
    const float* __restrict__ bias,
    float* __restrict__ C, int ldc, long sC,
    int M, int N, int K)
{
    A  += (long)blockIdx.z * sA;
    Bw += (long)blockIdx.z * sB;
    C  += (long)blockIdx.z * sC;
    __shared__ float As[16][68];
    __shared__ float Bs[16][68];
    int tid = threadIdx.x;
    int tx = tid & 15, ty = tid >> 4;
    int row0 = blockIdx.y * 64, col0 = blockIdx.x * 64;
    int lm = tid >> 2, lk = (tid & 3) << 2;
    float acc[4][4] = {{0.f}};

    for (int k0 = 0; k0 < K; k0 += 16) {
        float4 va = make_float4(0.f, 0.f, 0.f, 0.f);
        float4 vb = make_float4(0.f, 0.f, 0.f, 0.f);
        if (row0 + lm < M) va = *(const float4*)(A + (long)(row0 + lm) * lda + k0 + lk);
        if (col0 + lm < N) vb = *(const float4*)(Bw + (long)(col0 + lm) * ldb + k0 + lk);
        __syncthreads();
        As[lk][lm] = va.x; As[lk+1][lm] = va.y; As[lk+2][lm] = va.z; As[lk+3][lm] = va.w;
        Bs[lk][lm] = vb.x; Bs[lk+1][lm] = vb.y; Bs[lk+2][lm] = vb.z; Bs[lk+3][lm] = vb.w;
        __syncthreads();
#pragma unroll
        for (int kk = 0; kk < 16; kk++) {
            float4 a = *(const float4*)&As[kk][ty << 2];
            float4 b = *(const float4*)&Bs[kk][tx << 2];
            acc[0][0] += a.x*b.x; acc[0][1] += a.x*b.y; acc[0][2] += a.x*b.z; acc[0][3] += a.x*b.w;
            acc[1][0] += a.y*b.x; acc[1][1] += a.y*b.y; acc[1][2] += a.y*b.z; acc[1][3] += a.y*b.w;
            acc[2][0] += a.z*b.x; acc[2][1] += a.z*b.y; acc[2][2] += a.z*b.z; acc[2][3] += a.z*b.w;
            acc[3][0] += a.w*b.x; acc[3][1] += a.w*b.y; acc[3][2] += a.w*b.z; acc[3][3] += a.w*b.w;
        }
    }
#pragma unroll
    for (int i = 0; i < 4; i++) {
        int gm = row0 + (ty << 2) + i;
        if (gm >= M) continue;
#pragma unroll
        for (int j = 0; j < 4; j++) {
            int gn = col0 + (tx << 2) + j;
            if (gn >= N) continue;
            float v = acc[i][j];
            if (bias) v += __ldg(&bias[gn]);
            C[(long)gm * ldc + gn] = v;
        }
    }
}

// ---------------- 128x128 split-bf16 tensor-core GEMM ----------------
// C[M,N] = (Ahi+Alo)[M,K] @ (Bhi+Blo)[N,K]^T (+bias).
// expmode: writes fexp(v) instead of v, and rowsum[m] += sum_n fexp(v).
// 256 thr = 8 warps (4M x 2N), warp tile 32x64, K chunk 16.
__global__ void __launch_bounds__(256) k_mma128(
    const __nv_bfloat16* __restrict__ Ahi, const __nv_bfloat16* __restrict__ Alo,
    const __nv_bfloat16* __restrict__ Bhi, const __nv_bfloat16* __restrict__ Blo,
    const float* __restrict__ bias,
    float* __restrict__ C, long ldc,
    float* __restrict__ rowsum, int expmode,
    int M, int N, int K)
{
    __shared__ __nv_bfloat16 As[2][128][18];
    __shared__ __nv_bfloat16 Bs[2][128][18];
    int tid = threadIdx.x;
    int warp = tid >> 5, lane = tid & 31;
    int wm = warp >> 1, wn = warp & 1;
    int g = lane >> 2, tig = lane & 3;
    int m0 = blockIdx.y * 128, n0 = blockIdx.x * 128;

    float c[2][8][4];
#pragma unroll
    for (int mt = 0; mt < 2; mt++)
#pragma unroll
        for (int s = 0; s < 8; s++)
#pragma unroll
            for (int q = 0; q < 4; q++) c[mt][s][q] = 0.f;

    for (int kc = 0; kc < K; kc += 16) {
        __syncthreads();
#pragma unroll
        for (int it = 0; it < 4; it++) {
            int idx = it * 256 + tid;
            int row = idx >> 3, pr = idx & 7;
            {
                int gm = m0 + row;
                u32 vh = 0u, vl = 0u;
                if (gm < M) {
                    long gi = (long)gm * K + kc + pr * 2;
                    vh = *(const u32*)(Ahi + gi);
                    vl = *(const u32*)(Alo + gi);
                }
                *(u32*)&As[0][row][pr * 2] = vh;
                *(u32*)&As[1][row][pr * 2] = vl;
            }
            {
                int gn = n0 + row;
                u32 vh = 0u, vl = 0u;
                if (gn < N) {
                    long gi = (long)gn * K + kc + pr * 2;
                    vh = *(const u32*)(Bhi + gi);
                    vl = *(const u32*)(Blo + gi);
                }
                *(u32*)&Bs[0][row][pr * 2] = vh;
                *(u32*)&Bs[1][row][pr * 2] = vl;
            }
        }
        __syncthreads();

        u32 ah[2][4], al[2][4];
#pragma unroll
        for (int mt = 0; mt < 2; mt++) {
            int ar = wm * 32 + mt * 16 + g;
            ah[mt][0] = *(u32*)&As[0][ar][tig * 2];
            ah[mt][1] = *(u32*)&As[0][ar + 8][tig * 2];
            ah[mt][2] = *(u32*)&As[0][ar][tig * 2 + 8];
            ah[mt][3] = *(u32*)&As[0][ar + 8][tig * 2 + 8];
            al[mt][0] = *(u32*)&As[1][ar][tig * 2];
            al[mt][1] = *(u32*)&As[1][ar + 8][tig * 2];
            al[mt][2] = *(u32*)&As[1][ar][tig * 2 + 8];
            al[mt][3] = *(u32*)&As[1][ar + 8][tig * 2 + 8];
        }
#pragma unroll
        for (int sub = 0; sub < 8; sub++) {
            int bn = wn * 64 + sub * 8 + g;
            u32 bh[2], bl[2];
            bh[0] = *(u32*)&Bs[0][bn][tig * 2];
            bh[1] = *(u32*)&Bs[0][bn][tig * 2 + 8];
            bl[0] = *(u32*)&Bs[1][bn][tig * 2];
            bl[1] = *(u32*)&Bs[1][bn][tig * 2 + 8];
#pragma unroll
            for (int mt = 0; mt < 2; mt++) {
                mma_bf16(c[mt][sub], ah[mt], bh);   // hi*hi
                mma_bf16(c[mt][sub], ah[mt], bl);   // hi*lo
                mma_bf16(c[mt][sub], al[mt], bh);   // lo*hi
            }
        }
    }

#pragma unroll
    for (int mt = 0; mt < 2; mt++) {
        int gmA = m0 + wm * 32 + mt * 16 + g;
        int gmB = gmA + 8;
        float sA = 0.f, sB = 0.f;
#pragma unroll
        for (int sub = 0; sub < 8; sub++) {
            int gn = n0 + wn * 64 + sub * 8 + tig * 2;
            if (gn < N) {
                float v0 = c[mt][sub][0], v1 = c[mt][sub][1];
                float v2 = c[mt][sub][2], v3 = c[mt][sub][3];
                if (bias) {
                    float b0 = __ldg(&bias[gn]), b1 = __ldg(&bias[gn + 1]);
                    v0 += b0; v1 += b1; v2 += b0; v3 += b1;
                }
                if (expmode) { v0 = fexp(v0); v1 = fexp(v1); v2 = fexp(v2); v3 = fexp(v3); }
                if (gmA < M) *(float2*)(C + (long)gmA * ldc + gn) = make_float2(v0, v1);
                if (gmB < M) *(float2*)(C + (long)gmB * ldc + gn) = make_float2(v2, v3);
                sA += v0 + v1; sB += v2 + v3;
            }
        }
        if (rowsum) {
            sA += __shfl_xor_sync(0xffffffffu, sA, 1);
            sA += __shfl_xor_sync(0xffffffffu, sA, 2);
            sB += __shfl_xor_sync(0xffffffffu, sB, 1);
            sB += __shfl_xor_sync(0xffffffffu, sB, 2);
            if (tig == 0) {
                if (gmA < M) atomicAdd(rowsum + gmA, sA);
                if (gmB < M) atomicAdd(rowsum + gmB, sB);
            }
        }
    }
}

// ---------------- persistent bi-GRU encoder (unchanged from R8) ----------------
__global__ void __launch_bounds__(384, 1) k_enc(
    const float* __restrict__ Whh_f, const float* __restrict__ Whh_b,
    const float* __restrict__ bhh_f, const float* __restrict__ bhh_b)
{
    __shared__ float hs[16 * 404];
    __shared__ float ghs[24 * 16];
    __shared__ float bsh[24];

    int dir = (int)(blockIdx.x / 50);
    int jb  = (int)(blockIdx.x % 50);
    int j0  = jb * 8;
    const float* Whh = dir ? Whh_b : Whh_f;
    const float* bhh = dir ? bhh_b : bhh_f;
    const float* GI  = d_S + (dir ? OGI1 : OGI0);
    float* OUT = d_S + (dir ? OHB : OHF);
    int tid = threadIdx.x;

    int kp = tid & 15;
    int rgi = (tid >> 4) & 3;
    int qg = tid >> 6;
    int kbase = kp * 25;

    if (tid < 24) { int gate = tid >> 3, jl = tid & 7; bsh[tid] = bhh[gate * 400 + j0 + jl]; }

    float Wreg[4][25];
#pragma unroll
    for (int i = 0; i < 4; i++) {
        int q = qg * 4 + i;
        int gate = q >> 3, jl = q & 7;
        const float* wr = Whh + (long)(gate * 400 + j0 + jl) * 400 + kbase;
#pragma unroll
        for (int kk = 0; kk < 25; kk++) Wreg[i][kk] = wr[kk];
    }
    __syncthreads();

    for (int t = 0; t < TENC; ++t) {
        int p = t & 1;
        const float4* Hin4 = (const float4*)d_Hbuf[dir][p];
        float* Hout = d_Hbuf[dir][p ^ 1];

        float ir = 0.f, iz = 0.f, ig = 0.f;
        int time = dir ? (TENC - 1 - t) : t;
        if (tid < 128) {
            int rr = tid & 15, jj = tid >> 4;
            long gib = ((long)time * Bb + rr) * H3 + j0 + jj;
            ir = GI[gib]; iz = GI[gib + 400]; ig = GI[gib + 800];
        }

        for (int i4 = tid; i4 < 1600; i4 += 384) {
            float4 v = __ldcg(Hin4 + i4);
            int row = i4 / 100, c4 = (i4 % 100) << 2;
            *(float4*)&hs[row * 404 + c4] = v;
        }
        __syncthreads();

        float acc[4][4];
#pragma unroll
        for (int i = 0; i < 4; i++)
#pragma unroll
            for (int j = 0; j < 4; j++) acc[i][j] = 0.f;

        const float* h0 = hs + (rgi * 4 + 0) * 404 + kbase;
        const float* h1 = hs + (rgi * 4 + 1) * 404 + kbase;
        const float* h2 = hs + (rgi * 4 + 2) * 404 + kbase;
        const float* h3 = hs + (rgi * 4 + 3) * 404 + kbase;
#pragma unroll
        for (int kk = 0; kk < 25; kk++) {
            float hv0 = h0[kk], hv1 = h1[kk], hv2 = h2[kk], hv3 = h3[kk];
#pragma unroll
            for (int i = 0; i < 4; i++) {
                float w = Wreg[i][kk];
                acc[i][0] += w * hv0;
                acc[i][1] += w * hv1;
                acc[i][2] += w * hv2;
                acc[i][3] += w * hv3;
            }
        }

#pragma unroll
        for (int i = 0; i < 4; i++)
#pragma unroll
            for (int j = 0; j < 4; j++) {
                float v = acc[i][j];
                v += __shfl_xor_sync(0xffffffffu, v, 1);
                v += __shfl_xor_sync(0xffffffffu, v, 2);
                v += __shfl_xor_sync(0xffffffffu, v, 4);
                v += __shfl_xor_sync(0xffffffffu, v, 8);
                acc[i][j] = v;
            }
        if (kp == 0) {
#pragma unroll
            for (int i = 0; i < 4; i++) {
                float bb = bsh[qg * 4 + i];
#pragma unroll
                for (int j = 0; j < 4; j++)
                    ghs[(qg * 4 + i) * 16 + (rgi * 4 + j)] = acc[i][j] + bb;
            }
        }
        __syncthreads();

        if (tid < 128) {
            int rr = tid & 15, jj = tid >> 4;
            float hr_ = ghs[jj * 16 + rr];
            float hz_ = ghs[(8 + jj) * 16 + rr];
            float hg_ = ghs[(16 + jj) * 16 + rr];
            float hp  = hs[rr * 404 + j0 + jj];
            float rg_ = fsig(ir + hr_);
            float zg = fsig(iz + hz_);
            float gg = tanhf(ig + rg_ * hg_);
            float hn = (1.f - zg) * gg + zg * hp;
            Hout[rr * 400 + j0 + jj] = hn;
            OUT[((long)time * Bb + rr) * Hh + j0 + jj] = hn;
        }
        __syncthreads();
        if (tid == 0) {
            __threadfence();
            unsigned a = atomicAdd(&g_barcnt[dir], 1u);
            if (a == 50u * (unsigned)(t + 1) - 1u) {
                atomicAdd(&g_bargen[dir], 1u);
            } else {
                while (__ldcg((const unsigned*)&g_bargen[dir]) < (unsigned)(t + 1)) { __nanosleep(32); }
            }
            __threadfence();
        }
        __syncthreads();
    }
}

// ---------------- enc_out (B,T,H) and its transpose (B,H,T) ----------------
__global__ void k_encout() {
    long idx = (long)blockIdx.x * blockDim.x + threadIdx.x;
    if (idx >= (long)Bb * TENC * Hh) return;
    int b = (int)(idx / (TENC * Hh));
    int rem = (int)(idx % (TENC * Hh));
    int t = rem / Hh, h = rem % Hh;
    long src = ((long)t * Bb + b) * Hh + h;
    float v = d_S[OHF + src] + d_S[OHB + src];
    d_S[OEO + idx] = v;
    d_S[OEOT + (long)b * (Hh * TENC) + (long)h * TENC + t] = v;
}

// ---------------- decoder init ----------------
__global__ void k_dec_init(const float* __restrict__ slot) {
    int idx = blockIdx.x * blockDim.x + threadIdx.x;
    if (idx >= SB * Hh) return;
    int n = idx / Hh, h = idx % Hh;
    int s = n >> 4, b = n & 15;
    d_S[OH + idx]   = d_S[OHF + ((long)(TENC - 1) * Bb + b) * Hh + h]
                    + d_S[OHB + ((long)b) * Hh + h];
    d_S[ODIN + idx] = slot[s * Hh + h];
}

// ---------------- decoder GRU gates; zero rowsum + bf16 split of h ----------------
__global__ void k_dec_gates() {
    int idx = blockIdx.x * blockDim.x + threadIdx.x;
    if (idx < SB) d_S[ORSUM + idx] = 0.f;
    if (idx >= SB * Hh) return;
    int n = idx / Hh, j = idx % Hh;
    long gb = (long)n * H3 + j;
    float ir = d_S[OGI + gb], iz = d_S[OGI + gb + 400], ig = d_S[OGI + gb + 800];
    float hr = d_S[OGH + gb], hz = d_S[OGH + gb + 400], hg = d_S[OGH + gb + 800];
    float hp = d_S[OH + idx];
    float r = fsig(ir + hr);
    float z = fsig(iz + hz);
    float g = tanhf(ig + r * hg);
    float hn = (1.f - z) * g + z * hp;
    d_S[OH + idx] = hn;
    bsplit(hn, d_hhi[idx], d_hlo[idx]);
}

// ---------------- attention softmax over T=256 ----------------
__global__ void k_softmax_att() {
    int n = blockIdx.x, tid = threadIdx.x;
    __shared__ float red[256];
    float x = d_S[OPROB + (long)n * TENC + tid];
    red[tid] = x; __syncthreads();
    for (int o = 128; o; o >>= 1) { if (tid < o) red[tid] = fmaxf(red[tid], red[tid + o]); __syncthreads(); }
    float m = red[0]; __syncthreads();
    float e = fexp(x - m);
    red[tid] = e; __syncthreads();
    for (int o = 128; o; o >>= 1) { if (tid < o) red[tid] += red[tid + o]; __syncthreads(); }
    d_S[OPROB + (long)n * TENC + tid] = e / red[0];
}

// ---------------- sw (p_gen ratio) and (t==0) gate outputs ----------------
__global__ void k_sw_gate(const float* __restrict__ Wr, const float* __restrict__ br,
                          const float* __restrict__ Wg, const float* __restrict__ bg,
                          float* __restrict__ out, int t) {
    int warp = (blockIdx.x * blockDim.x + threadIdx.x) >> 5;
    int lane = threadIdx.x & 31;
    if (warp >= SB) return;
    int n = warp;
    float s = 0.f;
    for (int j = lane; j < H3; j += 32) {
        float v = (j < 400) ? d_S[OH + (long)n * Hh + j]
                : (j < 800) ? d_S[OCTX + (long)n * Hh + j - 400]
                            : d_S[ODIN + (long)n * Hh + j - 800];
        s += v * Wr[j];
    }
    for (int o = 16; o; o >>= 1) s += __shfl_xor_sync(0xffffffffu, s, o);
    if (lane == 0) d_S[OSW + n] = fsig(s + br[0]);
    if (t == 0) {
        for (int g = 0; g < Gg; g++) {
            float a = 0.f;
            for (int j = lane; j < Hh; j += 32) a += d_S[OCTX + (long)n * Hh + j] * Wg[g * Hh + j];
            for (int o = 16; o; o >>= 1) a += __shfl_xor_sync(0xffffffffu, a, o);
            if (lane == 0) out[PTR_OUT + (long)n * Gg + g] = a + bg[g];
        }
    }
}

// ---------------- scale out in place: *= sw/rowsum ----------------
__global__ void k_final(float* __restrict__ out, int t) {
    long idx = (long)blockIdx.x * blockDim.x + threadIdx.x;
    if (idx >= (long)SB * (Vv / 4)) return;
    int n = (int)(idx / (Vv / 4));
    int c = (int)(idx % (Vv / 4)) * 4;
    float sc = d_S[OSW + n] / d_S[ORSUM + n];
    float* p = out + ((long)n * TDEC + t) * Vv + c;
    float4 e = *(const float4*)p;
    e.x *= sc; e.y *= sc; e.z *= sc; e.w *= sc;
    *(float4*)p = e;
}

// ---------------- scatter-add pointer distribution ----------------
__global__ void k_scatter(float* __restrict__ out, const int* __restrict__ story, int t) {
    int idx = blockIdx.x * blockDim.x + threadIdx.x;
    if (idx >= SB * TENC) return;
    int n = idx >> 8, tt = idx & 255;
    int b = n & 15;
    int tok = story[b * TENC + tt];
    float v = (1.f - d_S[OSW + n]) * d_S[OPROB + (long)n * TENC + tt];
    atomicAdd(out + ((long)n * TDEC + t) * Vv + tok, v);
}

// ---------------- next decoder input ----------------
__global__ void k_next_din(const int* __restrict__ tb, const float* __restrict__ emb, int t) {
    int idx = blockIdx.x * blockDim.x + threadIdx.x;
    if (idx >= SB * Hh) return;
    int n = idx / Hh, h = idx % Hh;
    int s = n >> 4, b = n & 15;
    int tok = tb[(b * Ss + s) * TDEC + t];
    d_S[ODIN + idx] = emb[(long)tok * Hh + h];
}

// ---------------- host ----------------
extern "C" void kernel_launch(void* const* d_in, const int* in_sizes, int n_in,
                              void* d_out, int out_size) {
    const int*   story = (const int*)d_in[0];
    const int*   tb    = (const int*)d_in[1];
    const float* emb   = (const float*)d_in[2];
    const float* eWif  = (const float*)d_in[3];
    const float* eWhf  = (const float*)d_in[4];
    const float* ebif  = (const float*)d_in[5];
    const float* ebhf  = (const float*)d_in[6];
    const float* eWib  = (const float*)d_in[7];
    const float* eWhb  = (const float*)d_in[8];
    const float* ebib  = (const float*)d_in[9];
    const float* ebhb  = (const float*)d_in[10];
    const float* dWi   = (const float*)d_in[11];
    const float* dWh   = (const float*)d_in[12];
    const float* dbi   = (const float*)d_in[13];
    const float* dbh   = (const float*)d_in[14];
    const float* Wr    = (const float*)d_in[15];
    const float* br    = (const float*)d_in[16];
    const float* Wg    = (const float*)d_in[17];
    const float* bg    = (const float*)d_in[18];
    const float* slot  = (const float*)d_in[19];
    float* out = (float*)d_out;

    float* S = nullptr;
    cudaGetSymbolAddress((void**)&S, d_S);
    float* pGI0  = S + OGI0;
    float* pGI1  = S + OGI1;
    float* pEO   = S + OEO;
    float* pEOT  = S + OEOT;
    float* pH    = S + OH;
    float* pDIN  = S + ODIN;
    float* pGI   = S + OGI;
    float* pGH   = S + OGH;
    float* pPROB = S + OPROB;
    float* pCTX  = S + OCTX;
    float* pRS   = S + ORSUM;

    __nv_bfloat16 *xhi, *xlo, *wfhi, *wflo, *wbhi, *wblo, *ehi, *elo, *hhi, *hlo;
    cudaGetSymbolAddress((void**)&xhi, d_xhi);
    cudaGetSymbolAddress((void**)&xlo, d_xlo);
    cudaGetSymbolAddress((void**)&wfhi, d_wfhi);
    cudaGetSymbolAddress((void**)&wflo, d_wflo);
    cudaGetSymbolAddress((void**)&wbhi, d_wbhi);
    cudaGetSymbolAddress((void**)&wblo, d_wblo);
    cudaGetSymbolAddress((void**)&ehi, d_ehi);
    cudaGetSymbolAddress((void**)&elo, d_elo);
    cudaGetSymbolAddress((void**)&hhi, d_hhi);
    cudaGetSymbolAddress((void**)&hlo, d_hlo);

    k_init<<<32, 256>>>();
    k_embconv<<<(int)(((long)Vv * Hh + 255) / 256), 256>>>(emb);
    k_embed<<<(TENC * Bb * Hh + 255) / 256, 256>>>(story);
    k_wsplit<<<(H3 * Hh + 255) / 256, 256>>>(eWif, wfhi, wflo, H3 * Hh);
    k_wsplit<<<(H3 * Hh + 255) / 256, 256>>>(eWib, wbhi, wblo, H3 * Hh);

    // GI via tensor cores: (4096 x 1200 x 400)
    k_mma128<<<dim3(10, 32), 256>>>(xhi, xlo, wfhi, wflo, ebif, pGI0, H3, nullptr, 0, TENC * Bb, H3, Hh);
    k_mma128<<<dim3(10, 32), 256>>>(xhi, xlo, wbhi, wblo, ebib, pGI1, H3, nullptr, 0, TENC * Bb, H3, Hh);

    // persistent bidirectional GRU
    k_enc<<<100, 384>>>(eWhf, eWhb, ebhf, ebhb);

    k_encout<<<(Bb * TENC * Hh + 255) / 256, 256>>>();
    k_dec_init<<<(SB * Hh + 255) / 256, 256>>>(slot);

    for (int t = 0; t < TDEC; t++) {
        k_sgemm<<<dim3(19, 8, 1), 256>>>(pDIN, Hh, 0, dWi, Hh, 0, dbi, pGI, H3, 0, SB, H3, Hh);
        k_sgemm<<<dim3(19, 8, 1), 256>>>(pH,   Hh, 0, dWh, Hh, 0, dbh, pGH, H3, 0, SB, H3, Hh);
        k_dec_gates<<<(SB * Hh + 255) / 256, 256>>>();

        k_sgemm<<<dim3(4, 1, Bb), 256>>>(pH, Bb * Hh, Hh, pEO, Hh, (long)TENC * Hh,
                                         nullptr, pPROB, Bb * TENC, TENC, Ss, TENC, Hh);
        k_softmax_att<<<SB, 256>>>();
        k_sgemm<<<dim3(7, 1, Bb), 256>>>(pPROB, Bb * TENC, TENC, pEOT, TENC, (long)Hh * TENC,
                                         nullptr, pCTX, Bb * Hh, Hh, Ss, Hh, TENC);

        k_sw_gate<<<60, 256>>>(Wr, br, Wg, bg, out, t);

        // tensor-core logits: writes exp(logit) straight into out, accumulates rowsum
        k_mma128<<<dim3(141, 4), 256>>>(hhi, hlo, ehi, elo, nullptr,
                                        out + (long)t * Vv, (long)TDEC * Vv, pRS, 1, SB, Vv, Hh);
        k_final<<<(SB * (Vv / 4) + 255) / 256, 256>>>(out, t);
        k_scatter<<<SB, 256>>>(out, story, t);

        k_next_din<<<(SB * Hh + 255) / 256, 256>>>(tb, emb, t);
    }
}